// round 13
// baseline (speedup 1.0000x reference)
#include <cuda_runtime.h>
#include <cuda_bf16.h>
#include <cuda_fp16.h>
#include <math.h>
#include <float.h>
#include <stdint.h>

// Problem constants (fixed by reference setup_inputs)
#define DIM   1024
#define HS    128
#define NKV   2
#define T_SEQ 2048
#define BT_MAX 8192   // B*T = 4*2048

// ---------------- scratch (static device allocations; no cudaMalloc) -------
__device__ __half  g_xh   [BT_MAX * DIM];   // x fp16 hi
__device__ __half  g_xl   [BT_MAX * DIM];   // x fp16 lo residual
__device__ __half  g_q16  [BT_MAX * 256];   // rope'd+scaled Q, single fp16
__device__ __half  g_k16  [BT_MAX * 128];   // rope'd K, single fp16
__device__ __half  g_v16  [BT_MAX * 128];   // V, single fp16
__device__ __half  g_ath  [BT_MAX * 256];   // attention out fp16 hi
__device__ __half  g_atl  [BT_MAX * 256];   // attention out fp16 lo
__device__ __half  g_w16  [512 * DIM];      // Wcat single fp16
__device__ __half  g_wo16 [DIM * 256];      // Wo single fp16
__device__ float2  g_trig [T_SEQ * 64];     // (cos, sin) per (t, pair)

// ============================================================================
// helpers
// ============================================================================
__device__ __forceinline__ uint32_t smem_u32(const void* p) {
    uint32_t a;
    asm("{ .reg .u64 t; cvta.to.shared.u64 t, %1; cvt.u32.u64 %0, t; }"
        : "=r"(a) : "l"(p));
    return a;
}

__device__ __forceinline__ void mma_f16(float c[4], const uint32_t a[4],
                                        const uint32_t b[2]) {
    asm volatile(
        "mma.sync.aligned.m16n8k16.row.col.f32.f16.f16.f32 "
        "{%0,%1,%2,%3}, {%4,%5,%6,%7}, {%8,%9}, {%0,%1,%2,%3};"
        : "+f"(c[0]), "+f"(c[1]), "+f"(c[2]), "+f"(c[3])
        : "r"(a[0]), "r"(a[1]), "r"(a[2]), "r"(a[3]), "r"(b[0]), "r"(b[1]));
}

__device__ __forceinline__ void ldsm_x4(uint32_t r[4], uint32_t addr) {
    asm volatile("ldmatrix.sync.aligned.m8n8.x4.shared.b16 {%0,%1,%2,%3}, [%4];"
                 : "=r"(r[0]), "=r"(r[1]), "=r"(r[2]), "=r"(r[3]) : "r"(addr));
}
__device__ __forceinline__ void ldsm_x4_t(uint32_t r[4], uint32_t addr) {
    asm volatile("ldmatrix.sync.aligned.m8n8.x4.trans.shared.b16 {%0,%1,%2,%3}, [%4];"
                 : "=r"(r[0]), "=r"(r[1]), "=r"(r[2]), "=r"(r[3]) : "r"(addr));
}

#define CP_A16(dst, src) \
    asm volatile("cp.async.cg.shared.global [%0], [%1], 16;" \
                 :: "r"(dst), "l"(src) : "memory")
#define CP_COMMIT() asm volatile("cp.async.commit_group;" ::: "memory")
#define CP_WAIT0()  asm volatile("cp.async.wait_group 0;" ::: "memory")

// fp16 hi/lo split of a scalar pair -> packed half2 words
__device__ __forceinline__ void pack2h(float x, float y, uint32_t& hi, uint32_t& lo) {
    __half2 h = __float22half2_rn(make_float2(x, y));
    __half2 l = __float22half2_rn(
        make_float2(x - __low2float(h), y - __high2float(h)));
    hi = *(uint32_t*)&h; lo = *(uint32_t*)&l;
}
__device__ __forceinline__ uint32_t packh2(float x, float y) {
    __half2 h = __float22half2_rn(make_float2(x, y));
    return *(uint32_t*)&h;
}

// MUFU exp2: 1 instruction/value. ex2(-huge) -> 0 exactly.
__device__ __forceinline__ float ex2(float y) {
    float r;
    asm("ex2.approx.ftz.f32 %0, %1;" : "=f"(r) : "f"(y));
    return r;
}

// Swizzle for 128-col 16-bit tiles (256B rows), 16B chunks (attention)
__device__ __forceinline__ uint32_t sw256(int row, int col) {
    int chunk = col >> 3;
    return (uint32_t)(row * 256 + (((chunk ^ (row & 7)) << 4) | ((col & 7) << 1)));
}
// Swizzle for 64-col fp16 tiles (128B rows), 8 chunks of 16B (GEMM)
__device__ __forceinline__ uint32_t sw128h(int row, int chunk) {
    return (uint32_t)(row * 128 + ((chunk ^ (row & 7)) << 4));
}

// ---------------------------------------------------------------------------
// split_x: x fp32 -> fp16 hi/lo
// ---------------------------------------------------------------------------
__global__ void split_x_kernel(const float* __restrict__ x)
{
    int i = blockIdx.x * blockDim.x + threadIdx.x;
    const int TOT = BT_MAX * DIM / 4;
    if (i >= TOT) return;
    float4 v = ((const float4*)x)[i];
    uint2 hi, lo;
    pack2h(v.x, v.y, hi.x, lo.x);
    pack2h(v.z, v.w, hi.y, lo.y);
    *(uint2*)(g_xh + i * 4) = hi;
    *(uint2*)(g_xl + i * 4) = lo;
}

// ---------------------------------------------------------------------------
// Weight concat + fp16 convert + trig table (one launch)
// ---------------------------------------------------------------------------
__global__ void prep_kernel(const float* __restrict__ Wq,
                            const float* __restrict__ Wk,
                            const float* __restrict__ Wv,
                            const float* __restrict__ Wo)
{
    int i = blockIdx.x * blockDim.x + threadIdx.x;
    const int WCAT4 = 512 * DIM / 4;
    const int WO4   = DIM * 256 / 4;
    const int TRIG  = T_SEQ * 64;
    if (i < WCAT4) {
        int row = i >> 8;
        float4 v;
        if (row < 256)       v = ((const float4*)Wq)[i];
        else if (row < 384)  v = ((const float4*)Wk)[i - 256 * 256];
        else                 v = ((const float4*)Wv)[i - 384 * 256];
        uint2 w;
        w.x = packh2(v.x, v.y);
        w.y = packh2(v.z, v.w);
        *(uint2*)(g_w16 + i * 4) = w;
    } else if (i < WCAT4 + WO4) {
        int j = i - WCAT4;
        float4 v = ((const float4*)Wo)[j];
        uint2 w;
        w.x = packh2(v.x, v.y);
        w.y = packh2(v.z, v.w);
        *(uint2*)(g_wo16 + j * 4) = w;
    } else if (i < WCAT4 + WO4 + TRIG) {
        int j = i - WCAT4 - WO4;
        int t = j >> 6, k = j & 63;
        float theta = exp2f(-(float)k * (13.287712379549449f / 32.0f));
        float s, c;
        sincosf((float)t * theta, &s, &c);
        g_trig[j] = make_float2(c, s);
    }
}

// ---------------------------------------------------------------------------
// HMMA GEMM NT (2xFP16): C[M,N] = (Ah+Al)[M,K] * B16[N,K]^T.
// Single-barrier cp.async double-buffered pipeline (frozen WIN state).
// ---------------------------------------------------------------------------
#define GEMM_SMEM 98304

__device__ __forceinline__ void rope_epi_store(int r, int c, float x0, float x1)
{
    const float qscale = 0.08838834764831845f * 1.4426950408889634f;
    int t = r & (T_SEQ - 1);
    if (c < 384) {
        int i = (c & 127) >> 1;
        float2 cs = g_trig[t * 64 + i];
        float y0 = x0 * cs.x - x1 * cs.y;
        float y1 = x1 * cs.x + x0 * cs.y;
        if (c < 256) {
            y0 *= qscale; y1 *= qscale;
            *(uint32_t*)(g_q16 + (size_t)r * 256 + c) = packh2(y0, y1);
        } else {
            *(uint32_t*)(g_k16 + (size_t)r * 128 + (c - 256)) = packh2(y0, y1);
        }
    } else {
        *(uint32_t*)(g_v16 + (size_t)r * 128 + (c - 384)) = packh2(x0, x1);
    }
}

__global__ __launch_bounds__(256, 2)
void gemm_f16_kernel(const __half* __restrict__ Ah,
                     const __half* __restrict__ Al,
                     const __half* __restrict__ B16,
                     float* __restrict__ C, int M, int N, int K, int ldc,
                     int epi)
{
    extern __shared__ __align__(16) char smp[];
    const uint32_t sb = smem_u32(smp);

    const int tid = threadIdx.x;
    const int wid = tid >> 5;
    const int lane = tid & 31;
    const int m0 = blockIdx.x * 128;
    const int n0 = blockIdx.y * 128;
    const int wm = wid & 3;
    const int wn = wid >> 2;

    float acc[2][8][4];
#pragma unroll
    for (int mf = 0; mf < 2; mf++)
#pragma unroll
        for (int nf = 0; nf < 8; nf++)
#pragma unroll
            for (int q = 0; q < 4; q++) acc[mf][nf][q] = 0.f;

    const int KT = K >> 6;    // BK = 64

    auto fill = [&](int buf, int kt) {
        const uint32_t base = sb + buf * 49152;
#pragma unroll
        for (int i = 0; i < 4; i++) {
            int u = tid + i * 256;
            int row = u >> 3, ch = u & 7;
            uint32_t off = sw128h(row, ch);
            size_t sA = (size_t)(m0 + row) * K + kt * 64 + ch * 8;
            size_t sB = (size_t)(n0 + row) * K + kt * 64 + ch * 8;
            CP_A16(base + off,         Ah  + sA);
            CP_A16(base + 16384 + off, Al  + sA);
            CP_A16(base + 32768 + off, B16 + sB);
        }
        CP_COMMIT();
    };

    fill(0, 0);

    for (int kt = 0; kt < KT; kt++) {
        const int buf = kt & 1;
        CP_WAIT0();
        __syncthreads();
        if (kt + 1 < KT) fill(buf ^ 1, kt + 1);

        const uint32_t ab = sb + buf * 49152;
        const uint32_t bb = ab + 32768;
#pragma unroll
        for (int ks = 0; ks < 4; ks++) {
            uint32_t ah[2][4], al[2][4];
#pragma unroll
            for (int mf = 0; mf < 2; mf++) {
                int row = wm * 32 + mf * 16 + (lane & 15);
                int chunk = ks * 2 + (lane >> 4);
                uint32_t ad = ab + sw128h(row, chunk);
                ldsm_x4(ah[mf], ad);
                ldsm_x4(al[mf], ad + 16384);
            }
            uint32_t bh[8][2];
#pragma unroll
            for (int np = 0; np < 4; np++) {
                int row = wn * 64 + np * 16 + ((lane >> 4) << 3) + (lane & 7);
                int chunk = ks * 2 + ((lane >> 3) & 1);
                uint32_t t[4];
                ldsm_x4(t, bb + sw128h(row, chunk));
                bh[np * 2][0] = t[0]; bh[np * 2][1] = t[1];
                bh[np * 2 + 1][0] = t[2]; bh[np * 2 + 1][1] = t[3];
            }
#pragma unroll
            for (int mf = 0; mf < 2; mf++)
#pragma unroll
                for (int nf = 0; nf < 8; nf++) {
                    mma_f16(acc[mf][nf], ah[mf], bh[nf]);
                    mma_f16(acc[mf][nf], al[mf], bh[nf]);
                }
        }
    }

    if (epi == 0) {
#pragma unroll
        for (int mf = 0; mf < 2; mf++)
#pragma unroll
            for (int nf = 0; nf < 8; nf++) {
                int row = m0 + wm * 32 + mf * 16 + (lane >> 2);
                int col = n0 + wn * 64 + nf * 8 + (lane & 3) * 2;
                *(float2*)(C + (size_t)row * ldc + col) =
                    make_float2(acc[mf][nf][0], acc[mf][nf][1]);
                *(float2*)(C + (size_t)(row + 8) * ldc + col) =
                    make_float2(acc[mf][nf][2], acc[mf][nf][3]);
            }
    } else {
#pragma unroll
        for (int mf = 0; mf < 2; mf++)
#pragma unroll
            for (int nf = 0; nf < 8; nf++) {
                int row = m0 + wm * 32 + mf * 16 + (lane >> 2);
                int col = n0 + wn * 64 + nf * 8 + (lane & 3) * 2;
                rope_epi_store(row,     col, acc[mf][nf][0], acc[mf][nf][1]);
                rope_epi_store(row + 8, col, acc[mf][nf][2], acc[mf][nf][3]);
            }
    }
}

// ---------------------------------------------------------------------------
// Flash attention, software-pipelined with SPLIT K/V fill schedule:
// body j: wait -> sync -> fill{K(j+2), V(j+1)} -> S(j+1) + PV(j) -> softmax(j+1)
// K and V each double-buffered: smem = 64KB -> 3 CTAs/SM.
// Layout: K_b at b*16384 (b=0,1); V_b at 32768 + b*16384; Q staged in V_1.
// ---------------------------------------------------------------------------
#define ATT2_SMEM 65536

__global__ __launch_bounds__(128, 3)
void attn_reg_kernel(const __half* __restrict__ q_g,
                     const __half* __restrict__ k_g,
                     const __half* __restrict__ v_g, int T)
{
    extern __shared__ __align__(16) char smp[];
    const uint32_t sb = smem_u32(smp);

    const int tid = threadIdx.x;
    const int wid = tid >> 5;
    const int lane = tid & 31;
    const int bh = blockIdx.y;
    const int b  = bh >> 1;
    const int h  = bh & 1;

    // Orbit-balanced mt map (heavy/light pairing across co-resident bids)
    const int bx = blockIdx.x;
    const int oo = bx & 3;
    const int qq = bx >> 2;
    const int pp_ = (qq & 1) ? (qq ^ 4) : qq;
    const int mt = (pp_ & 1) ? (4 * oo + (pp_ >> 1)) : (31 - 4 * oo - (pp_ >> 1));
    const int m0 = mt * 64;

    const size_t rb = (size_t)b * T;

    auto KB = [&](int bf) { return sb + bf * 16384; };
    auto VB = [&](int bf) { return sb + 32768 + bf * 16384; };

    auto fillK = [&](int bf, int j) {
        const uint32_t kb = KB(bf);
        const int n0v = j * 64;
#pragma unroll
        for (int i = 0; i < 8; i++) {
            int u = tid + i * 128;
            int row = u >> 4, ch = u & 15;
            uint32_t off = sw256(row, ch * 8);
            size_t src = (size_t)(rb + n0v + row) * 128 + ch * 8;
            CP_A16(kb + off, k_g + src);
        }
    };
    auto fillV = [&](int bf, int j) {
        const uint32_t vb = VB(bf);
        const int n0v = j * 64;
#pragma unroll
        for (int i = 0; i < 8; i++) {
            int u = tid + i * 128;
            int row = u >> 4, ch = u & 15;
            uint32_t off = sw256(row, ch * 8);
            size_t src = (size_t)(rb + n0v + row) * 128 + ch * 8;
            CP_A16(vb + off, v_g + src);
        }
    };

    // ---- prologue: stage Q (into V_1 slot) + fill K0,V0 (+K1) ----
    {
        const uint32_t qstage = VB(1);
#pragma unroll
        for (int i = 0; i < 8; i++) {
            int u = tid + i * 128;
            int row = u >> 4, ch = u & 15;
            uint32_t off = sw256(row, ch * 8);
            size_t src = (rb + m0 + row) * 256 + h * 128 + ch * 8;
            CP_A16(qstage + off, q_g + src);
        }
        fillK(0, 0);
        fillV(0, 0);
        if (mt >= 1) fillK(1, 1);
        CP_COMMIT();
        CP_WAIT0();
        __syncthreads();
    }

    uint32_t qf[8][4];
#pragma unroll
    for (int ks = 0; ks < 8; ks++) {
        int row = wid * 16 + (lane & 15);
        int chunk = ks * 2 + (lane >> 4);
        ldsm_x4(qf[ks], VB(1) + sw256(row, chunk * 8));
    }
    // V_1 is refilled in body 0 AFTER its barrier — extraction is safe.

    float mr0 = -1e30f, mr1 = -1e30f, lr0 = 0.f, lr1 = 0.f;
    float oacc[16][4];
#pragma unroll
    for (int nf = 0; nf < 16; nf++)
#pragma unroll
        for (int q = 0; q < 4; q++) oacc[nf][q] = 0.f;

    uint32_t pp[4][4];   // P fragments (single fp16) for the pending PV

    auto computeS = [&](uint32_t kb, float sacc[8][4]) {
#pragma unroll
        for (int nf = 0; nf < 8; nf++)
#pragma unroll
            for (int q = 0; q < 4; q++) sacc[nf][q] = 0.f;
#pragma unroll
        for (int ks = 0; ks < 8; ks++) {
#pragma unroll
            for (int ng = 0; ng < 4; ng++) {
                int row = ng * 16 + ((lane >> 4) << 3) + (lane & 7);
                int chunk = ks * 2 + ((lane >> 3) & 1);
                uint32_t t[4];
                ldsm_x4(t, kb + sw256(row, chunk * 8));
                uint32_t b0[2] = {t[0], t[1]}, b1[2] = {t[2], t[3]};
                mma_f16(sacc[ng * 2],     qf[ks], b0);
                mma_f16(sacc[ng * 2 + 1], qf[ks], b1);
            }
        }
    };

    auto softmax_pack = [&](float sacc[8][4], int jj) {
        if (jj == mt) {
            int grow0 = m0 + wid * 16 + (lane >> 2);
            int grow1 = grow0 + 8;
            int cbase = jj * 64 + (lane & 3) * 2;
#pragma unroll
            for (int nf = 0; nf < 8; nf++) {
                int c = cbase + nf * 8;
                if (c     > grow0) sacc[nf][0] = -1e30f;
                if (c + 1 > grow0) sacc[nf][1] = -1e30f;
                if (c     > grow1) sacc[nf][2] = -1e30f;
                if (c + 1 > grow1) sacc[nf][3] = -1e30f;
            }
        }
        float mx0 = -1e30f, mx1 = -1e30f;
#pragma unroll
        for (int nf = 0; nf < 8; nf++) {
            mx0 = fmaxf(mx0, fmaxf(sacc[nf][0], sacc[nf][1]));
            mx1 = fmaxf(mx1, fmaxf(sacc[nf][2], sacc[nf][3]));
        }
        mx0 = fmaxf(mx0, __shfl_xor_sync(0xffffffffu, mx0, 1));
        mx0 = fmaxf(mx0, __shfl_xor_sync(0xffffffffu, mx0, 2));
        mx1 = fmaxf(mx1, __shfl_xor_sync(0xffffffffu, mx1, 1));
        mx1 = fmaxf(mx1, __shfl_xor_sync(0xffffffffu, mx1, 2));

        float mn0 = fmaxf(mr0, mx0), mn1 = fmaxf(mr1, mx1);
        float corr0 = ex2(mr0 - mn0), corr1 = ex2(mr1 - mn1);
        mr0 = mn0; mr1 = mn1;

        float sum0 = 0.f, sum1 = 0.f;
#pragma unroll
        for (int nf = 0; nf < 8; nf++) {
            sacc[nf][0] = ex2(sacc[nf][0] - mn0);
            sacc[nf][1] = ex2(sacc[nf][1] - mn0);
            sacc[nf][2] = ex2(sacc[nf][2] - mn1);
            sacc[nf][3] = ex2(sacc[nf][3] - mn1);
            sum0 += sacc[nf][0] + sacc[nf][1];
            sum1 += sacc[nf][2] + sacc[nf][3];
        }
        sum0 += __shfl_xor_sync(0xffffffffu, sum0, 1);
        sum0 += __shfl_xor_sync(0xffffffffu, sum0, 2);
        sum1 += __shfl_xor_sync(0xffffffffu, sum1, 1);
        sum1 += __shfl_xor_sync(0xffffffffu, sum1, 2);
        lr0 = lr0 * corr0 + sum0;
        lr1 = lr1 * corr1 + sum1;

        if (__any_sync(0xffffffffu, (corr0 < 1.0f) | (corr1 < 1.0f))) {
#pragma unroll
            for (int nf = 0; nf < 16; nf++) {
                oacc[nf][0] *= corr0; oacc[nf][1] *= corr0;
                oacc[nf][2] *= corr1; oacc[nf][3] *= corr1;
            }
        }
#pragma unroll
        for (int kc = 0; kc < 4; kc++) {
            pp[kc][0] = packh2(sacc[2 * kc][0],     sacc[2 * kc][1]);
            pp[kc][1] = packh2(sacc[2 * kc][2],     sacc[2 * kc][3]);
            pp[kc][2] = packh2(sacc[2 * kc + 1][0], sacc[2 * kc + 1][1]);
            pp[kc][3] = packh2(sacc[2 * kc + 1][2], sacc[2 * kc + 1][3]);
        }
    };

    auto computePV = [&](uint32_t vb) {
#pragma unroll
        for (int ks2 = 0; ks2 < 4; ks2++) {
            int vrow = ks2 * 16 + (lane & 15);
#pragma unroll
            for (int g = 0; g < 8; g++) {
                int chunk = g * 2 + (lane >> 4);
                uint32_t vh[4];
                ldsm_x4_t(vh, vb + sw256(vrow, chunk * 8));
                uint32_t vh0[2] = {vh[0], vh[1]}, vh1[2] = {vh[2], vh[3]};
                mma_f16(oacc[g * 2],     pp[ks2], vh0);
                mma_f16(oacc[g * 2 + 1], pp[ks2], vh1);
            }
        }
    };

    // ---- prologue compute: S(0) -> P(0) ----
    {
        float sacc[8][4];
        computeS(KB(0), sacc);
        softmax_pack(sacc, 0);
    }

    // ---- pipelined main loop: fill{K(j+2),V(j+1)} ; S(j+1) + PV(j) ----
    for (int j = 0; j < mt; j++) {
        CP_WAIT0();        // fills from body j-1 (K(j+1), V(j)) complete
        __syncthreads();   // publish; all warps past reads of overwritten slots
        {
            if (j + 2 <= mt) fillK(j & 1, j + 2);     // K(j+2) -> slot j%2
            fillV((j + 1) & 1, j + 1);                // V(j+1) -> slot (j+1)%2
            CP_COMMIT();
        }

        float sacc[8][4];
        computeS(KB((j + 1) & 1), sacc);
        computePV(VB(j & 1));

        softmax_pack(sacc, j + 1);
    }

    // ---- final PV(mt) ----
    computePV(VB(mt & 1));

    // ---- epilogue: normalize + fp16 hi/lo store ----
    float inv0 = 1.0f / lr0;
    float inv1 = 1.0f / lr1;
    size_t row0 = rb + m0 + wid * 16 + (lane >> 2);
#pragma unroll
    for (int nf = 0; nf < 16; nf++) {
        int col = h * 128 + nf * 8 + (lane & 3) * 2;
        uint32_t hi, lo;
        pack2h(oacc[nf][0] * inv0, oacc[nf][1] * inv0, hi, lo);
        *(uint32_t*)(g_ath + row0 * 256 + col) = hi;
        *(uint32_t*)(g_atl + row0 * 256 + col) = lo;
        pack2h(oacc[nf][2] * inv1, oacc[nf][3] * inv1, hi, lo);
        *(uint32_t*)(g_ath + (row0 + 8) * 256 + col) = hi;
        *(uint32_t*)(g_atl + (row0 + 8) * 256 + col) = lo;
    }
}

// ---------------------------------------------------------------------------
extern "C" void kernel_launch(void* const* d_in, const int* in_sizes, int n_in,
                              void* d_out, int out_size)
{
    const float* x  = (const float*)d_in[0];
    const float* Wq = (const float*)d_in[1];
    const float* Wk = (const float*)d_in[2];
    const float* Wv = (const float*)d_in[3];
    const float* Wo = (const float*)d_in[4];

    const int BT = in_sizes[0] / DIM;  // 8192
    const int T  = T_SEQ;
    const int B  = BT / T;

    __half *xh, *xl, *q16, *k16, *v16, *ath, *atl, *w16, *wo16;
    cudaGetSymbolAddress((void**)&xh,   g_xh);
    cudaGetSymbolAddress((void**)&xl,   g_xl);
    cudaGetSymbolAddress((void**)&q16,  g_q16);
    cudaGetSymbolAddress((void**)&k16,  g_k16);
    cudaGetSymbolAddress((void**)&v16,  g_v16);
    cudaGetSymbolAddress((void**)&ath,  g_ath);
    cudaGetSymbolAddress((void**)&atl,  g_atl);
    cudaGetSymbolAddress((void**)&w16,  g_w16);
    cudaGetSymbolAddress((void**)&wo16, g_wo16);

    cudaFuncSetAttribute(gemm_f16_kernel,
                         cudaFuncAttributeMaxDynamicSharedMemorySize, GEMM_SMEM);
    cudaFuncSetAttribute(attn_reg_kernel,
                         cudaFuncAttributeMaxDynamicSharedMemorySize, ATT2_SMEM);

    // 1) split x + (concat/convert weights + trig)
    {
        int tot = BT * DIM / 4;
        split_x_kernel<<<(tot + 255) / 256, 256>>>(x);
        int wt = 512 * DIM / 4 + DIM * 256 / 4 + T_SEQ * 64;
        prep_kernel<<<(wt + 255) / 256, 256>>>(Wq, Wk, Wv, Wo);
    }

    // 2) fused QKV projection + rope + convert epilogue
    {
        dim3 grid(BT / 128, 512 / 128);
        gemm_f16_kernel<<<grid, 256, GEMM_SMEM>>>(xh, xl, w16, nullptr,
                                                  BT, 512, DIM, 512, 1);
    }

    // 3) flash attention (pipelined, split K/V fills, 3 CTAs/SM)
    {
        dim3 grid(T / 64, B * NKV);
        attn_reg_kernel<<<grid, 128, ATT2_SMEM>>>(q16, k16, v16, T);
    }

    // 4) output projection
    {
        dim3 grid(BT / 128, DIM / 128);
        gemm_f16_kernel<<<grid, 256, GEMM_SMEM>>>(ath, atl, wo16,
                                                  (float*)d_out, BT, DIM, 256,
                                                  DIM, 0);
    }
}

// round 14
// speedup vs baseline: 1.0933x; 1.0933x over previous
#include <cuda_runtime.h>
#include <cuda_bf16.h>
#include <cuda_fp16.h>
#include <math.h>
#include <float.h>
#include <stdint.h>

// Problem constants (fixed by reference setup_inputs)
#define DIM   1024
#define HS    128
#define NKV   2
#define T_SEQ 2048
#define BT_MAX 8192   // B*T = 4*2048

// ---------------- scratch (static device allocations; no cudaMalloc) -------
__device__ __half  g_q16  [BT_MAX * 256];   // rope'd+scaled Q, single fp16
__device__ __half  g_k16  [BT_MAX * 128];   // rope'd K, single fp16
__device__ __half  g_v16  [BT_MAX * 128];   // V, single fp16
__device__ __half  g_ath  [BT_MAX * 256];   // attention out fp16 hi
__device__ __half  g_atl  [BT_MAX * 256];   // attention out fp16 lo
__device__ __half  g_w16  [512 * DIM];      // Wcat single fp16
__device__ __half  g_wo16 [DIM * 256];      // Wo single fp16
__device__ float2  g_trig [T_SEQ * 64];     // (cos, sin) per (t, pair)

// ============================================================================
// helpers
// ============================================================================
__device__ __forceinline__ uint32_t smem_u32(const void* p) {
    uint32_t a;
    asm("{ .reg .u64 t; cvta.to.shared.u64 t, %1; cvt.u32.u64 %0, t; }"
        : "=r"(a) : "l"(p));
    return a;
}

__device__ __forceinline__ void mma_f16(float c[4], const uint32_t a[4],
                                        const uint32_t b[2]) {
    asm volatile(
        "mma.sync.aligned.m16n8k16.row.col.f32.f16.f16.f32 "
        "{%0,%1,%2,%3}, {%4,%5,%6,%7}, {%8,%9}, {%0,%1,%2,%3};"
        : "+f"(c[0]), "+f"(c[1]), "+f"(c[2]), "+f"(c[3])
        : "r"(a[0]), "r"(a[1]), "r"(a[2]), "r"(a[3]), "r"(b[0]), "r"(b[1]));
}

__device__ __forceinline__ void ldsm_x4(uint32_t r[4], uint32_t addr) {
    asm volatile("ldmatrix.sync.aligned.m8n8.x4.shared.b16 {%0,%1,%2,%3}, [%4];"
                 : "=r"(r[0]), "=r"(r[1]), "=r"(r[2]), "=r"(r[3]) : "r"(addr));
}
__device__ __forceinline__ void ldsm_x4_t(uint32_t r[4], uint32_t addr) {
    asm volatile("ldmatrix.sync.aligned.m8n8.x4.trans.shared.b16 {%0,%1,%2,%3}, [%4];"
                 : "=r"(r[0]), "=r"(r[1]), "=r"(r[2]), "=r"(r[3]) : "r"(addr));
}

#define CP_A16(dst, src) \
    asm volatile("cp.async.cg.shared.global [%0], [%1], 16;" \
                 :: "r"(dst), "l"(src) : "memory")
#define CP_COMMIT() asm volatile("cp.async.commit_group;" ::: "memory")
#define CP_WAIT0()  asm volatile("cp.async.wait_group 0;" ::: "memory")

// fp16 hi/lo split of a scalar pair -> packed half2 words
__device__ __forceinline__ void pack2h(float x, float y, uint32_t& hi, uint32_t& lo) {
    __half2 h = __float22half2_rn(make_float2(x, y));
    __half2 l = __float22half2_rn(
        make_float2(x - __low2float(h), y - __high2float(h)));
    hi = *(uint32_t*)&h; lo = *(uint32_t*)&l;
}
__device__ __forceinline__ uint32_t packh2(float x, float y) {
    __half2 h = __float22half2_rn(make_float2(x, y));
    return *(uint32_t*)&h;
}

// MUFU exp2: 1 instruction/value. ex2(-huge) -> 0 exactly.
__device__ __forceinline__ float ex2(float y) {
    float r;
    asm("ex2.approx.ftz.f32 %0, %1;" : "=f"(r) : "f"(y));
    return r;
}

// Swizzle for 128-col 16-bit tiles (256B rows), 16B chunks (attention)
__device__ __forceinline__ uint32_t sw256(int row, int col) {
    int chunk = col >> 3;
    return (uint32_t)(row * 256 + (((chunk ^ (row & 7)) << 4) | ((col & 7) << 1)));
}
// Swizzle for 64-col fp16 tiles (128B rows), 8 chunks of 16B (GEMM)
__device__ __forceinline__ uint32_t sw128h(int row, int chunk) {
    return (uint32_t)(row * 128 + ((chunk ^ (row & 7)) << 4));
}

// ---------------------------------------------------------------------------
// Weight concat + fp16 convert + trig table (one launch)
// ---------------------------------------------------------------------------
__global__ void prep_kernel(const float* __restrict__ Wq,
                            const float* __restrict__ Wk,
                            const float* __restrict__ Wv,
                            const float* __restrict__ Wo)
{
    int i = blockIdx.x * blockDim.x + threadIdx.x;
    const int WCAT4 = 512 * DIM / 4;
    const int WO4   = DIM * 256 / 4;
    const int TRIG  = T_SEQ * 64;
    if (i < WCAT4) {
        int row = i >> 8;
        float4 v;
        if (row < 256)       v = ((const float4*)Wq)[i];
        else if (row < 384)  v = ((const float4*)Wk)[i - 256 * 256];
        else                 v = ((const float4*)Wv)[i - 384 * 256];
        uint2 w;
        w.x = packh2(v.x, v.y);
        w.y = packh2(v.z, v.w);
        *(uint2*)(g_w16 + i * 4) = w;
    } else if (i < WCAT4 + WO4) {
        int j = i - WCAT4;
        float4 v = ((const float4*)Wo)[j];
        uint2 w;
        w.x = packh2(v.x, v.y);
        w.y = packh2(v.z, v.w);
        *(uint2*)(g_wo16 + j * 4) = w;
    } else if (i < WCAT4 + WO4 + TRIG) {
        int j = i - WCAT4 - WO4;
        int t = j >> 6, k = j & 63;
        float theta = exp2f(-(float)k * (13.287712379549449f / 32.0f));
        float s, c;
        sincosf((float)t * theta, &s, &c);
        g_trig[j] = make_float2(c, s);
    }
}

// ---------------------------------------------------------------------------
// rope epilogue store (GEMM1)
// ---------------------------------------------------------------------------
__device__ __forceinline__ void rope_epi_store(int r, int c, float x0, float x1)
{
    const float qscale = 0.08838834764831845f * 1.4426950408889634f;
    int t = r & (T_SEQ - 1);
    if (c < 384) {
        int i = (c & 127) >> 1;
        float2 cs = g_trig[t * 64 + i];
        float y0 = x0 * cs.x - x1 * cs.y;
        float y1 = x1 * cs.x + x0 * cs.y;
        if (c < 256) {
            y0 *= qscale; y1 *= qscale;
            *(uint32_t*)(g_q16 + (size_t)r * 256 + c) = packh2(y0, y1);
        } else {
            *(uint32_t*)(g_k16 + (size_t)r * 128 + (c - 256)) = packh2(y0, y1);
        }
    } else {
        *(uint32_t*)(g_v16 + (size_t)r * 128 + (c - 384)) = packh2(x0, x1);
    }
}

// ---------------------------------------------------------------------------
// GEMM1: qkv = x (fp32, split inline to fp16 hi/lo) * Wcat16^T, rope epilogue.
// 128x128 CTA tile, BK=64, 256 threads. A: LDG fp32 -> convert -> STS (two
// 16-reg batches interleaved with compute halves). B: cp.async double-buffer.
// Stage s at s*49152: Ah +0, Al +16384, B +32768.
// ---------------------------------------------------------------------------
#define GEMM_SMEM 98304

__global__ __launch_bounds__(256, 2)
void gemm_x_kernel(const float* __restrict__ X,
                   const __half* __restrict__ B16,
                   int M, int N, int K)
{
    extern __shared__ __align__(16) char smp[];
    const uint32_t sb = smem_u32(smp);

    const int tid = threadIdx.x;
    const int wid = tid >> 5;
    const int lane = tid & 31;
    const int m0 = blockIdx.x * 128;
    const int n0 = blockIdx.y * 128;
    const int wm = wid & 3;
    const int wn = wid >> 2;

    float acc[2][8][4];
#pragma unroll
    for (int mf = 0; mf < 2; mf++)
#pragma unroll
        for (int nf = 0; nf < 8; nf++)
#pragma unroll
            for (int q = 0; q < 4; q++) acc[mf][nf][q] = 0.f;

    const int KT = K >> 6;    // 16

    // B fill: 1024 16B chunks / 256 threads = 4 cp.async per thread
    auto fillB = [&](int buf, int kt) {
        const uint32_t bbase = sb + buf * 49152 + 32768;
#pragma unroll
        for (int i = 0; i < 4; i++) {
            int u = tid + i * 256;
            int row = u >> 3, ch = u & 7;
            CP_A16(bbase + sw128h(row, ch),
                   B16 + (size_t)(n0 + row) * K + kt * 64 + ch * 8);
        }
        CP_COMMIT();
    };

    // A LDG batch: 4 float4 per thread (batch bsel in {0,1})
    auto ldgA = [&](int kt, int bsel, float4 vr[4]) {
#pragma unroll
        for (int i = 0; i < 4; i++) {
            int u = tid + (bsel * 4 + i) * 256;    // 0..2047
            int row = u >> 4, q4 = u & 15;
            vr[i] = *(const float4*)(X + (size_t)(m0 + row) * K + kt * 64 + q4 * 4);
        }
    };
    // A convert + STS batch
    auto stsA = [&](int buf, int bsel, const float4 vr[4]) {
        const uint32_t abase = sb + buf * 49152;
#pragma unroll
        for (int i = 0; i < 4; i++) {
            int u = tid + (bsel * 4 + i) * 256;
            int row = u >> 4, q4 = u & 15;
            uint32_t off = sw128h(row, q4 >> 1) + (q4 & 1) * 8;
            uint32_t h0, l0, h1, l1;
            pack2h(vr[i].x, vr[i].y, h0, l0);
            pack2h(vr[i].z, vr[i].w, h1, l1);
            *(uint2*)(smp + (off + buf * 49152))        = make_uint2(h0, h1);
            *(uint2*)(smp + (off + buf * 49152 + 16384)) = make_uint2(l0, l1);
        }
        (void)abase;
    };

    // ---- prologue: stage 0 ----
    {
        float4 v0[4], v1[4];
        ldgA(0, 0, v0);
        ldgA(0, 1, v1);
        fillB(0, 0);
        stsA(0, 0, v0);
        stsA(0, 1, v1);
        CP_WAIT0();
        __syncthreads();
    }

    for (int kt = 0; kt < KT; kt++) {
        const int buf = kt & 1;
        const bool pre = (kt + 1 < KT);

        // issue B(kt+1) + first A batch load
        float4 vr[4];
        if (pre) {
            fillB(buf ^ 1, kt + 1);
            ldgA(kt + 1, 0, vr);
        }

        const uint32_t ab = sb + buf * 49152;
        const uint32_t bb = ab + 32768;

        // ---- compute half 1 (ks = 0,1) ----
#pragma unroll
        for (int ks = 0; ks < 2; ks++) {
            uint32_t ah[2][4], al[2][4];
#pragma unroll
            for (int mf = 0; mf < 2; mf++) {
                int row = wm * 32 + mf * 16 + (lane & 15);
                int chunk = ks * 2 + (lane >> 4);
                uint32_t ad = ab + sw128h(row, chunk);
                ldsm_x4(ah[mf], ad);
                ldsm_x4(al[mf], ad + 16384);
            }
            uint32_t bh[8][2];
#pragma unroll
            for (int np = 0; np < 4; np++) {
                int row = wn * 64 + np * 16 + ((lane >> 4) << 3) + (lane & 7);
                int chunk = ks * 2 + ((lane >> 3) & 1);
                uint32_t t[4];
                ldsm_x4(t, bb + sw128h(row, chunk));
                bh[np * 2][0] = t[0]; bh[np * 2][1] = t[1];
                bh[np * 2 + 1][0] = t[2]; bh[np * 2 + 1][1] = t[3];
            }
#pragma unroll
            for (int mf = 0; mf < 2; mf++)
#pragma unroll
                for (int nf = 0; nf < 8; nf++) {
                    mma_f16(acc[mf][nf], ah[mf], bh[nf]);
                    mma_f16(acc[mf][nf], al[mf], bh[nf]);
                }
        }

        // STS first A batch; load second
        if (pre) {
            stsA(buf ^ 1, 0, vr);
            ldgA(kt + 1, 1, vr);
        }

        // ---- compute half 2 (ks = 2,3) ----
#pragma unroll
        for (int ks = 2; ks < 4; ks++) {
            uint32_t ah[2][4], al[2][4];
#pragma unroll
            for (int mf = 0; mf < 2; mf++) {
                int row = wm * 32 + mf * 16 + (lane & 15);
                int chunk = ks * 2 + (lane >> 4);
                uint32_t ad = ab + sw128h(row, chunk);
                ldsm_x4(ah[mf], ad);
                ldsm_x4(al[mf], ad + 16384);
            }
            uint32_t bh[8][2];
#pragma unroll
            for (int np = 0; np < 4; np++) {
                int row = wn * 64 + np * 16 + ((lane >> 4) << 3) + (lane & 7);
                int chunk = ks * 2 + ((lane >> 3) & 1);
                uint32_t t[4];
                ldsm_x4(t, bb + sw128h(row, chunk));
                bh[np * 2][0] = t[0]; bh[np * 2][1] = t[1];
                bh[np * 2 + 1][0] = t[2]; bh[np * 2 + 1][1] = t[3];
            }
#pragma unroll
            for (int mf = 0; mf < 2; mf++)
#pragma unroll
                for (int nf = 0; nf < 8; nf++) {
                    mma_f16(acc[mf][nf], ah[mf], bh[nf]);
                    mma_f16(acc[mf][nf], al[mf], bh[nf]);
                }
        }

        if (pre) stsA(buf ^ 1, 1, vr);

        // wait B(kt+1) + publish A STS for next iter
        if (pre) {
            CP_WAIT0();
        }
        __syncthreads();
    }

    // rope + convert epilogue
#pragma unroll
    for (int mf = 0; mf < 2; mf++)
#pragma unroll
        for (int nf = 0; nf < 8; nf++) {
            int row = m0 + wm * 32 + mf * 16 + (lane >> 2);
            int col = n0 + wn * 64 + nf * 8 + (lane & 3) * 2;
            rope_epi_store(row,     col, acc[mf][nf][0], acc[mf][nf][1]);
            rope_epi_store(row + 8, col, acc[mf][nf][2], acc[mf][nf][3]);
        }
}

// ---------------------------------------------------------------------------
// GEMM2 (unchanged R12 WIN): out = (ath+atl) * Wo16^T, fp32 C.
// ---------------------------------------------------------------------------
__global__ __launch_bounds__(256, 2)
void gemm_f16_kernel(const __half* __restrict__ Ah,
                     const __half* __restrict__ Al,
                     const __half* __restrict__ B16,
                     float* __restrict__ C, int M, int N, int K, int ldc)
{
    extern __shared__ __align__(16) char smp[];
    const uint32_t sb = smem_u32(smp);

    const int tid = threadIdx.x;
    const int wid = tid >> 5;
    const int lane = tid & 31;
    const int m0 = blockIdx.x * 128;
    const int n0 = blockIdx.y * 128;
    const int wm = wid & 3;
    const int wn = wid >> 2;

    float acc[2][8][4];
#pragma unroll
    for (int mf = 0; mf < 2; mf++)
#pragma unroll
        for (int nf = 0; nf < 8; nf++)
#pragma unroll
            for (int q = 0; q < 4; q++) acc[mf][nf][q] = 0.f;

    const int KT = K >> 6;

    auto fill = [&](int buf, int kt) {
        const uint32_t base = sb + buf * 49152;
#pragma unroll
        for (int i = 0; i < 4; i++) {
            int u = tid + i * 256;
            int row = u >> 3, ch = u & 7;
            uint32_t off = sw128h(row, ch);
            size_t sA = (size_t)(m0 + row) * K + kt * 64 + ch * 8;
            size_t sB = (size_t)(n0 + row) * K + kt * 64 + ch * 8;
            CP_A16(base + off,         Ah  + sA);
            CP_A16(base + 16384 + off, Al  + sA);
            CP_A16(base + 32768 + off, B16 + sB);
        }
        CP_COMMIT();
    };

    fill(0, 0);

    for (int kt = 0; kt < KT; kt++) {
        const int buf = kt & 1;
        CP_WAIT0();
        __syncthreads();
        if (kt + 1 < KT) fill(buf ^ 1, kt + 1);

        const uint32_t ab = sb + buf * 49152;
        const uint32_t bb = ab + 32768;
#pragma unroll
        for (int ks = 0; ks < 4; ks++) {
            uint32_t ah[2][4], al[2][4];
#pragma unroll
            for (int mf = 0; mf < 2; mf++) {
                int row = wm * 32 + mf * 16 + (lane & 15);
                int chunk = ks * 2 + (lane >> 4);
                uint32_t ad = ab + sw128h(row, chunk);
                ldsm_x4(ah[mf], ad);
                ldsm_x4(al[mf], ad + 16384);
            }
            uint32_t bh[8][2];
#pragma unroll
            for (int np = 0; np < 4; np++) {
                int row = wn * 64 + np * 16 + ((lane >> 4) << 3) + (lane & 7);
                int chunk = ks * 2 + ((lane >> 3) & 1);
                uint32_t t[4];
                ldsm_x4(t, bb + sw128h(row, chunk));
                bh[np * 2][0] = t[0]; bh[np * 2][1] = t[1];
                bh[np * 2 + 1][0] = t[2]; bh[np * 2 + 1][1] = t[3];
            }
#pragma unroll
            for (int mf = 0; mf < 2; mf++)
#pragma unroll
                for (int nf = 0; nf < 8; nf++) {
                    mma_f16(acc[mf][nf], ah[mf], bh[nf]);
                    mma_f16(acc[mf][nf], al[mf], bh[nf]);
                }
        }
    }

#pragma unroll
    for (int mf = 0; mf < 2; mf++)
#pragma unroll
        for (int nf = 0; nf < 8; nf++) {
            int row = m0 + wm * 32 + mf * 16 + (lane >> 2);
            int col = n0 + wn * 64 + nf * 8 + (lane & 3) * 2;
            *(float2*)(C + (size_t)row * ldc + col) =
                make_float2(acc[mf][nf][0], acc[mf][nf][1]);
            *(float2*)(C + (size_t)(row + 8) * ldc + col) =
                make_float2(acc[mf][nf][2], acc[mf][nf][3]);
        }
}

// ---------------------------------------------------------------------------
// Flash attention (exact R12 WIN): software-pipelined, triple-buffered K/V,
// MUFU ex2 softmax. Q single fp16 frags in regs; P single fp16.
// Layout: K_b at b*16384 (b=0..2); V_b at 49152 + b*16384; Q staged in V_2.
// ---------------------------------------------------------------------------
#define ATT2_SMEM 98304

__global__ __launch_bounds__(128, 2)
void attn_reg_kernel(const __half* __restrict__ q_g,
                     const __half* __restrict__ k_g,
                     const __half* __restrict__ v_g, int T)
{
    extern __shared__ __align__(16) char smp[];
    const uint32_t sb = smem_u32(smp);

    const int tid = threadIdx.x;
    const int wid = tid >> 5;
    const int lane = tid & 31;
    const int bh = blockIdx.y;
    const int b  = bh >> 1;
    const int h  = bh & 1;

    const int bx = blockIdx.x;
    const int oo = bx & 3;
    const int qq = bx >> 2;
    const int pp_ = (qq & 1) ? (qq ^ 4) : qq;
    const int mt = (pp_ & 1) ? (4 * oo + (pp_ >> 1)) : (31 - 4 * oo - (pp_ >> 1));
    const int m0 = mt * 64;

    const size_t rb = (size_t)b * T;

    auto KB = [&](int bf) { return sb + bf * 16384; };
    auto VB = [&](int bf) { return sb + 49152 + bf * 16384; };

    auto fillKV = [&](int bf, int j) {
        const uint32_t kb = KB(bf);
        const uint32_t vb = VB(bf);
        const int n0v = j * 64;
#pragma unroll
        for (int i = 0; i < 8; i++) {
            int u = tid + i * 128;
            int row = u >> 4, ch = u & 15;
            uint32_t off = sw256(row, ch * 8);
            size_t src = (size_t)(rb + n0v + row) * 128 + ch * 8;
            CP_A16(kb + off, k_g + src);
            CP_A16(vb + off, v_g + src);
        }
        CP_COMMIT();
    };

    // ---- prologue: stage Q (into V_2 slot) + fill KV tile 0 ----
    {
        const uint32_t qstage = VB(2);
#pragma unroll
        for (int i = 0; i < 8; i++) {
            int u = tid + i * 128;
            int row = u >> 4, ch = u & 15;
            uint32_t off = sw256(row, ch * 8);
            size_t src = (rb + m0 + row) * 256 + h * 128 + ch * 8;
            CP_A16(qstage + off, q_g + src);
        }
        const int n0v = 0;
#pragma unroll
        for (int i = 0; i < 8; i++) {
            int u = tid + i * 128;
            int row = u >> 4, ch = u & 15;
            uint32_t off = sw256(row, ch * 8);
            size_t src = (size_t)(rb + n0v + row) * 128 + ch * 8;
            CP_A16(KB(0) + off, k_g + src);
            CP_A16(VB(0) + off, v_g + src);
        }
        CP_COMMIT();
        CP_WAIT0();
        __syncthreads();
    }

    uint32_t qf[8][4];
#pragma unroll
    for (int ks = 0; ks < 8; ks++) {
        int row = wid * 16 + (lane & 15);
        int chunk = ks * 2 + (lane >> 4);
        ldsm_x4(qf[ks], VB(2) + sw256(row, chunk * 8));
    }

    if (mt >= 1) fillKV(1, 1);

    float mr0 = -1e30f, mr1 = -1e30f, lr0 = 0.f, lr1 = 0.f;
    float oacc[16][4];
#pragma unroll
    for (int nf = 0; nf < 16; nf++)
#pragma unroll
        for (int q = 0; q < 4; q++) oacc[nf][q] = 0.f;

    uint32_t pp[4][4];

    auto computeS = [&](uint32_t kb, float sacc[8][4]) {
#pragma unroll
        for (int nf = 0; nf < 8; nf++)
#pragma unroll
            for (int q = 0; q < 4; q++) sacc[nf][q] = 0.f;
#pragma unroll
        for (int ks = 0; ks < 8; ks++) {
#pragma unroll
            for (int ng = 0; ng < 4; ng++) {
                int row = ng * 16 + ((lane >> 4) << 3) + (lane & 7);
                int chunk = ks * 2 + ((lane >> 3) & 1);
                uint32_t t[4];
                ldsm_x4(t, kb + sw256(row, chunk * 8));
                uint32_t b0[2] = {t[0], t[1]}, b1[2] = {t[2], t[3]};
                mma_f16(sacc[ng * 2],     qf[ks], b0);
                mma_f16(sacc[ng * 2 + 1], qf[ks], b1);
            }
        }
    };

    auto softmax_pack = [&](float sacc[8][4], int jj) {
        if (jj == mt) {
            int grow0 = m0 + wid * 16 + (lane >> 2);
            int grow1 = grow0 + 8;
            int cbase = jj * 64 + (lane & 3) * 2;
#pragma unroll
            for (int nf = 0; nf < 8; nf++) {
                int c = cbase + nf * 8;
                if (c     > grow0) sacc[nf][0] = -1e30f;
                if (c + 1 > grow0) sacc[nf][1] = -1e30f;
                if (c     > grow1) sacc[nf][2] = -1e30f;
                if (c + 1 > grow1) sacc[nf][3] = -1e30f;
            }
        }
        float mx0 = -1e30f, mx1 = -1e30f;
#pragma unroll
        for (int nf = 0; nf < 8; nf++) {
            mx0 = fmaxf(mx0, fmaxf(sacc[nf][0], sacc[nf][1]));
            mx1 = fmaxf(mx1, fmaxf(sacc[nf][2], sacc[nf][3]));
        }
        mx0 = fmaxf(mx0, __shfl_xor_sync(0xffffffffu, mx0, 1));
        mx0 = fmaxf(mx0, __shfl_xor_sync(0xffffffffu, mx0, 2));
        mx1 = fmaxf(mx1, __shfl_xor_sync(0xffffffffu, mx1, 1));
        mx1 = fmaxf(mx1, __shfl_xor_sync(0xffffffffu, mx1, 2));

        float mn0 = fmaxf(mr0, mx0), mn1 = fmaxf(mr1, mx1);
        float corr0 = ex2(mr0 - mn0), corr1 = ex2(mr1 - mn1);
        mr0 = mn0; mr1 = mn1;

        float sum0 = 0.f, sum1 = 0.f;
#pragma unroll
        for (int nf = 0; nf < 8; nf++) {
            sacc[nf][0] = ex2(sacc[nf][0] - mn0);
            sacc[nf][1] = ex2(sacc[nf][1] - mn0);
            sacc[nf][2] = ex2(sacc[nf][2] - mn1);
            sacc[nf][3] = ex2(sacc[nf][3] - mn1);
            sum0 += sacc[nf][0] + sacc[nf][1];
            sum1 += sacc[nf][2] + sacc[nf][3];
        }
        sum0 += __shfl_xor_sync(0xffffffffu, sum0, 1);
        sum0 += __shfl_xor_sync(0xffffffffu, sum0, 2);
        sum1 += __shfl_xor_sync(0xffffffffu, sum1, 1);
        sum1 += __shfl_xor_sync(0xffffffffu, sum1, 2);
        lr0 = lr0 * corr0 + sum0;
        lr1 = lr1 * corr1 + sum1;

        if (__any_sync(0xffffffffu, (corr0 < 1.0f) | (corr1 < 1.0f))) {
#pragma unroll
            for (int nf = 0; nf < 16; nf++) {
                oacc[nf][0] *= corr0; oacc[nf][1] *= corr0;
                oacc[nf][2] *= corr1; oacc[nf][3] *= corr1;
            }
        }
#pragma unroll
        for (int kc = 0; kc < 4; kc++) {
            pp[kc][0] = packh2(sacc[2 * kc][0],     sacc[2 * kc][1]);
            pp[kc][1] = packh2(sacc[2 * kc][2],     sacc[2 * kc][3]);
            pp[kc][2] = packh2(sacc[2 * kc + 1][0], sacc[2 * kc + 1][1]);
            pp[kc][3] = packh2(sacc[2 * kc + 1][2], sacc[2 * kc + 1][3]);
        }
    };

    auto computePV = [&](uint32_t vb) {
#pragma unroll
        for (int ks2 = 0; ks2 < 4; ks2++) {
            int vrow = ks2 * 16 + (lane & 15);
#pragma unroll
            for (int g = 0; g < 8; g++) {
                int chunk = g * 2 + (lane >> 4);
                uint32_t vh[4];
                ldsm_x4_t(vh, vb + sw256(vrow, chunk * 8));
                uint32_t vh0[2] = {vh[0], vh[1]}, vh1[2] = {vh[2], vh[3]};
                mma_f16(oacc[g * 2],     pp[ks2], vh0);
                mma_f16(oacc[g * 2 + 1], pp[ks2], vh1);
            }
        }
    };

    // ---- prologue compute: S(0) -> P(0) ----
    {
        float sacc[8][4];
        computeS(KB(0), sacc);
        softmax_pack(sacc, 0);
    }

    // ---- pipelined main loop: PV(j) + S(j+1) ----
    for (int j = 0; j < mt; j++) {
        const int bufc = j % 3;
        const int bufn = (j + 1) % 3;

        CP_WAIT0();
        __syncthreads();
        if (j + 2 <= mt) fillKV((j + 2) % 3, j + 2);

        float sacc[8][4];
        computeS(KB(bufn), sacc);
        computePV(VB(bufc));

        softmax_pack(sacc, j + 1);
    }

    // ---- final PV(mt) ----
    computePV(VB(mt % 3));

    // ---- epilogue: normalize + fp16 hi/lo store ----
    float inv0 = 1.0f / lr0;
    float inv1 = 1.0f / lr1;
    size_t row0 = rb + m0 + wid * 16 + (lane >> 2);
#pragma unroll
    for (int nf = 0; nf < 16; nf++) {
        int col = h * 128 + nf * 8 + (lane & 3) * 2;
        uint32_t hi, lo;
        pack2h(oacc[nf][0] * inv0, oacc[nf][1] * inv0, hi, lo);
        *(uint32_t*)(g_ath + row0 * 256 + col) = hi;
        *(uint32_t*)(g_atl + row0 * 256 + col) = lo;
        pack2h(oacc[nf][2] * inv1, oacc[nf][3] * inv1, hi, lo);
        *(uint32_t*)(g_ath + (row0 + 8) * 256 + col) = hi;
        *(uint32_t*)(g_atl + (row0 + 8) * 256 + col) = lo;
    }
}

// ---------------------------------------------------------------------------
extern "C" void kernel_launch(void* const* d_in, const int* in_sizes, int n_in,
                              void* d_out, int out_size)
{
    const float* x  = (const float*)d_in[0];
    const float* Wq = (const float*)d_in[1];
    const float* Wk = (const float*)d_in[2];
    const float* Wv = (const float*)d_in[3];
    const float* Wo = (const float*)d_in[4];

    const int BT = in_sizes[0] / DIM;  // 8192
    const int T  = T_SEQ;
    const int B  = BT / T;

    __half *q16, *k16, *v16, *ath, *atl, *w16, *wo16;
    cudaGetSymbolAddress((void**)&q16,  g_q16);
    cudaGetSymbolAddress((void**)&k16,  g_k16);
    cudaGetSymbolAddress((void**)&v16,  g_v16);
    cudaGetSymbolAddress((void**)&ath,  g_ath);
    cudaGetSymbolAddress((void**)&atl,  g_atl);
    cudaGetSymbolAddress((void**)&w16,  g_w16);
    cudaGetSymbolAddress((void**)&wo16, g_wo16);

    cudaFuncSetAttribute(gemm_x_kernel,
                         cudaFuncAttributeMaxDynamicSharedMemorySize, GEMM_SMEM);
    cudaFuncSetAttribute(gemm_f16_kernel,
                         cudaFuncAttributeMaxDynamicSharedMemorySize, GEMM_SMEM);
    cudaFuncSetAttribute(attn_reg_kernel,
                         cudaFuncAttributeMaxDynamicSharedMemorySize, ATT2_SMEM);

    // 1) prep (weights + trig) — x conversion now fused into GEMM1
    {
        int wt = 512 * DIM / 4 + DIM * 256 / 4 + T_SEQ * 64;
        prep_kernel<<<(wt + 255) / 256, 256>>>(Wq, Wk, Wv, Wo);
    }

    // 2) fused QKV projection (inline fp32->fp16 split) + rope epilogue
    {
        dim3 grid(BT / 128, 512 / 128);
        gemm_x_kernel<<<grid, 256, GEMM_SMEM>>>(x, w16, BT, 512, DIM);
    }

    // 3) flash attention (R12 WIN state)
    {
        dim3 grid(T / 64, B * NKV);
        attn_reg_kernel<<<grid, 128, ATT2_SMEM>>>(q16, k16, v16, T);
    }

    // 4) output projection
    {
        dim3 grid(BT / 128, DIM / 128);
        gemm_f16_kernel<<<grid, 256, GEMM_SMEM>>>(ath, atl, wo16,
                                                  (float*)d_out, BT, DIM, 256,
                                                  DIM);
    }
}

// round 15
// speedup vs baseline: 1.1781x; 1.0776x over previous
#include <cuda_runtime.h>
#include <cuda_bf16.h>
#include <cuda_fp16.h>
#include <math.h>
#include <float.h>
#include <stdint.h>

// Problem constants (fixed by reference setup_inputs)
#define DIM   1024
#define HS    128
#define NKV   2
#define T_SEQ 2048
#define BT_MAX 8192   // B*T = 4*2048

// ---------------- scratch (static device allocations; no cudaMalloc) -------
__device__ __half  g_q16  [BT_MAX * 256];   // rope'd+scaled Q, single fp16
__device__ __half  g_k16  [BT_MAX * 128];   // rope'd K, single fp16
__device__ __half  g_v16  [BT_MAX * 128];   // V, single fp16
__device__ __half  g_ath  [BT_MAX * 256];   // attention out, single fp16
__device__ __half  g_w16  [512 * DIM];      // Wcat single fp16
__device__ __half  g_wo16 [DIM * 256];      // Wo single fp16
__device__ float2  g_trig [T_SEQ * 64];     // (cos, sin) per (t, pair)

// ============================================================================
// helpers
// ============================================================================
__device__ __forceinline__ uint32_t smem_u32(const void* p) {
    uint32_t a;
    asm("{ .reg .u64 t; cvta.to.shared.u64 t, %1; cvt.u32.u64 %0, t; }"
        : "=r"(a) : "l"(p));
    return a;
}

__device__ __forceinline__ void mma_f16(float c[4], const uint32_t a[4],
                                        const uint32_t b[2]) {
    asm volatile(
        "mma.sync.aligned.m16n8k16.row.col.f32.f16.f16.f32 "
        "{%0,%1,%2,%3}, {%4,%5,%6,%7}, {%8,%9}, {%0,%1,%2,%3};"
        : "+f"(c[0]), "+f"(c[1]), "+f"(c[2]), "+f"(c[3])
        : "r"(a[0]), "r"(a[1]), "r"(a[2]), "r"(a[3]), "r"(b[0]), "r"(b[1]));
}

__device__ __forceinline__ void ldsm_x4(uint32_t r[4], uint32_t addr) {
    asm volatile("ldmatrix.sync.aligned.m8n8.x4.shared.b16 {%0,%1,%2,%3}, [%4];"
                 : "=r"(r[0]), "=r"(r[1]), "=r"(r[2]), "=r"(r[3]) : "r"(addr));
}
__device__ __forceinline__ void ldsm_x4_t(uint32_t r[4], uint32_t addr) {
    asm volatile("ldmatrix.sync.aligned.m8n8.x4.trans.shared.b16 {%0,%1,%2,%3}, [%4];"
                 : "=r"(r[0]), "=r"(r[1]), "=r"(r[2]), "=r"(r[3]) : "r"(addr));
}

#define CP_A16(dst, src) \
    asm volatile("cp.async.cg.shared.global [%0], [%1], 16;" \
                 :: "r"(dst), "l"(src) : "memory")
#define CP_COMMIT() asm volatile("cp.async.commit_group;" ::: "memory")
#define CP_WAIT0()  asm volatile("cp.async.wait_group 0;" ::: "memory")

// fp16 hi/lo split of a scalar pair -> packed half2 words
__device__ __forceinline__ void pack2h(float x, float y, uint32_t& hi, uint32_t& lo) {
    __half2 h = __float22half2_rn(make_float2(x, y));
    __half2 l = __float22half2_rn(
        make_float2(x - __low2float(h), y - __high2float(h)));
    hi = *(uint32_t*)&h; lo = *(uint32_t*)&l;
}
__device__ __forceinline__ uint32_t packh2(float x, float y) {
    __half2 h = __float22half2_rn(make_float2(x, y));
    return *(uint32_t*)&h;
}

// MUFU exp2: 1 instruction/value. ex2(-huge) -> 0 exactly.
__device__ __forceinline__ float ex2(float y) {
    float r;
    asm("ex2.approx.ftz.f32 %0, %1;" : "=f"(r) : "f"(y));
    return r;
}

// Swizzle for 128-col 16-bit tiles (256B rows), 16B chunks (attention)
__device__ __forceinline__ uint32_t sw256(int row, int col) {
    int chunk = col >> 3;
    return (uint32_t)(row * 256 + (((chunk ^ (row & 7)) << 4) | ((col & 7) << 1)));
}
// Swizzle for 64-col fp16 tiles (128B rows), 8 chunks of 16B (GEMM)
__device__ __forceinline__ uint32_t sw128h(int row, int chunk) {
    return (uint32_t)(row * 128 + ((chunk ^ (row & 7)) << 4));
}

// ---------------------------------------------------------------------------
// Weight concat + fp16 convert + trig table (one launch)
// ---------------------------------------------------------------------------
__global__ void prep_kernel(const float* __restrict__ Wq,
                            const float* __restrict__ Wk,
                            const float* __restrict__ Wv,
                            const float* __restrict__ Wo)
{
    int i = blockIdx.x * blockDim.x + threadIdx.x;
    const int WCAT4 = 512 * DIM / 4;
    const int WO4   = DIM * 256 / 4;
    const int TRIG  = T_SEQ * 64;
    if (i < WCAT4) {
        int row = i >> 8;
        float4 v;
        if (row < 256)       v = ((const float4*)Wq)[i];
        else if (row < 384)  v = ((const float4*)Wk)[i - 256 * 256];
        else                 v = ((const float4*)Wv)[i - 384 * 256];
        uint2 w;
        w.x = packh2(v.x, v.y);
        w.y = packh2(v.z, v.w);
        *(uint2*)(g_w16 + i * 4) = w;
    } else if (i < WCAT4 + WO4) {
        int j = i - WCAT4;
        float4 v = ((const float4*)Wo)[j];
        uint2 w;
        w.x = packh2(v.x, v.y);
        w.y = packh2(v.z, v.w);
        *(uint2*)(g_wo16 + j * 4) = w;
    } else if (i < WCAT4 + WO4 + TRIG) {
        int j = i - WCAT4 - WO4;
        int t = j >> 6, k = j & 63;
        float theta = exp2f(-(float)k * (13.287712379549449f / 32.0f));
        float s, c;
        sincosf((float)t * theta, &s, &c);
        g_trig[j] = make_float2(c, s);
    }
}

// ---------------------------------------------------------------------------
// rope epilogue store (GEMM1)
// ---------------------------------------------------------------------------
__device__ __forceinline__ void rope_epi_store(int r, int c, float x0, float x1)
{
    const float qscale = 0.08838834764831845f * 1.4426950408889634f;
    int t = r & (T_SEQ - 1);
    if (c < 384) {
        int i = (c & 127) >> 1;
        float2 cs = g_trig[t * 64 + i];
        float y0 = x0 * cs.x - x1 * cs.y;
        float y1 = x1 * cs.x + x0 * cs.y;
        if (c < 256) {
            y0 *= qscale; y1 *= qscale;
            *(uint32_t*)(g_q16 + (size_t)r * 256 + c) = packh2(y0, y1);
        } else {
            *(uint32_t*)(g_k16 + (size_t)r * 128 + (c - 256)) = packh2(y0, y1);
        }
    } else {
        *(uint32_t*)(g_v16 + (size_t)r * 128 + (c - 384)) = packh2(x0, x1);
    }
}

// ---------------------------------------------------------------------------
// GEMM1 (frozen R14 WIN): qkv = x (fp32 split inline) * Wcat16^T, rope epi.
// ---------------------------------------------------------------------------
#define GEMM_SMEM 98304

__global__ __launch_bounds__(256, 2)
void gemm_x_kernel(const float* __restrict__ X,
                   const __half* __restrict__ B16,
                   int M, int N, int K)
{
    extern __shared__ __align__(16) char smp[];
    const uint32_t sb = smem_u32(smp);

    const int tid = threadIdx.x;
    const int wid = tid >> 5;
    const int lane = tid & 31;
    const int m0 = blockIdx.x * 128;
    const int n0 = blockIdx.y * 128;
    const int wm = wid & 3;
    const int wn = wid >> 2;

    float acc[2][8][4];
#pragma unroll
    for (int mf = 0; mf < 2; mf++)
#pragma unroll
        for (int nf = 0; nf < 8; nf++)
#pragma unroll
            for (int q = 0; q < 4; q++) acc[mf][nf][q] = 0.f;

    const int KT = K >> 6;    // 16

    auto fillB = [&](int buf, int kt) {
        const uint32_t bbase = sb + buf * 49152 + 32768;
#pragma unroll
        for (int i = 0; i < 4; i++) {
            int u = tid + i * 256;
            int row = u >> 3, ch = u & 7;
            CP_A16(bbase + sw128h(row, ch),
                   B16 + (size_t)(n0 + row) * K + kt * 64 + ch * 8);
        }
        CP_COMMIT();
    };

    auto ldgA = [&](int kt, int bsel, float4 vr[4]) {
#pragma unroll
        for (int i = 0; i < 4; i++) {
            int u = tid + (bsel * 4 + i) * 256;
            int row = u >> 4, q4 = u & 15;
            vr[i] = *(const float4*)(X + (size_t)(m0 + row) * K + kt * 64 + q4 * 4);
        }
    };
    auto stsA = [&](int buf, int bsel, const float4 vr[4]) {
#pragma unroll
        for (int i = 0; i < 4; i++) {
            int u = tid + (bsel * 4 + i) * 256;
            int row = u >> 4, q4 = u & 15;
            uint32_t off = sw128h(row, q4 >> 1) + (q4 & 1) * 8;
            uint32_t h0, l0, h1, l1;
            pack2h(vr[i].x, vr[i].y, h0, l0);
            pack2h(vr[i].z, vr[i].w, h1, l1);
            *(uint2*)(smp + (off + buf * 49152))         = make_uint2(h0, h1);
            *(uint2*)(smp + (off + buf * 49152 + 16384)) = make_uint2(l0, l1);
        }
    };

    {
        float4 v0[4], v1[4];
        ldgA(0, 0, v0);
        ldgA(0, 1, v1);
        fillB(0, 0);
        stsA(0, 0, v0);
        stsA(0, 1, v1);
        CP_WAIT0();
        __syncthreads();
    }

    for (int kt = 0; kt < KT; kt++) {
        const int buf = kt & 1;
        const bool pre = (kt + 1 < KT);

        float4 vr[4];
        if (pre) {
            fillB(buf ^ 1, kt + 1);
            ldgA(kt + 1, 0, vr);
        }

        const uint32_t ab = sb + buf * 49152;
        const uint32_t bb = ab + 32768;

#pragma unroll
        for (int ks = 0; ks < 2; ks++) {
            uint32_t ah[2][4], al[2][4];
#pragma unroll
            for (int mf = 0; mf < 2; mf++) {
                int row = wm * 32 + mf * 16 + (lane & 15);
                int chunk = ks * 2 + (lane >> 4);
                uint32_t ad = ab + sw128h(row, chunk);
                ldsm_x4(ah[mf], ad);
                ldsm_x4(al[mf], ad + 16384);
            }
            uint32_t bh[8][2];
#pragma unroll
            for (int np = 0; np < 4; np++) {
                int row = wn * 64 + np * 16 + ((lane >> 4) << 3) + (lane & 7);
                int chunk = ks * 2 + ((lane >> 3) & 1);
                uint32_t t[4];
                ldsm_x4(t, bb + sw128h(row, chunk));
                bh[np * 2][0] = t[0]; bh[np * 2][1] = t[1];
                bh[np * 2 + 1][0] = t[2]; bh[np * 2 + 1][1] = t[3];
            }
#pragma unroll
            for (int mf = 0; mf < 2; mf++)
#pragma unroll
                for (int nf = 0; nf < 8; nf++) {
                    mma_f16(acc[mf][nf], ah[mf], bh[nf]);
                    mma_f16(acc[mf][nf], al[mf], bh[nf]);
                }
        }

        if (pre) {
            stsA(buf ^ 1, 0, vr);
            ldgA(kt + 1, 1, vr);
        }

#pragma unroll
        for (int ks = 2; ks < 4; ks++) {
            uint32_t ah[2][4], al[2][4];
#pragma unroll
            for (int mf = 0; mf < 2; mf++) {
                int row = wm * 32 + mf * 16 + (lane & 15);
                int chunk = ks * 2 + (lane >> 4);
                uint32_t ad = ab + sw128h(row, chunk);
                ldsm_x4(ah[mf], ad);
                ldsm_x4(al[mf], ad + 16384);
            }
            uint32_t bh[8][2];
#pragma unroll
            for (int np = 0; np < 4; np++) {
                int row = wn * 64 + np * 16 + ((lane >> 4) << 3) + (lane & 7);
                int chunk = ks * 2 + ((lane >> 3) & 1);
                uint32_t t[4];
                ldsm_x4(t, bb + sw128h(row, chunk));
                bh[np * 2][0] = t[0]; bh[np * 2][1] = t[1];
                bh[np * 2 + 1][0] = t[2]; bh[np * 2 + 1][1] = t[3];
            }
#pragma unroll
            for (int mf = 0; mf < 2; mf++)
#pragma unroll
                for (int nf = 0; nf < 8; nf++) {
                    mma_f16(acc[mf][nf], ah[mf], bh[nf]);
                    mma_f16(acc[mf][nf], al[mf], bh[nf]);
                }
        }

        if (pre) stsA(buf ^ 1, 1, vr);

        if (pre) {
            CP_WAIT0();
        }
        __syncthreads();
    }

#pragma unroll
    for (int mf = 0; mf < 2; mf++)
#pragma unroll
        for (int nf = 0; nf < 8; nf++) {
            int row = m0 + wm * 32 + mf * 16 + (lane >> 2);
            int col = n0 + wn * 64 + nf * 8 + (lane & 3) * 2;
            rope_epi_store(row,     col, acc[mf][nf][0], acc[mf][nf][1]);
            rope_epi_store(row + 8, col, acc[mf][nf][2], acc[mf][nf][3]);
        }
}

// ---------------------------------------------------------------------------
// GEMM2: out = A16[M,K] * Wo16[N,K]^T, fp32 C. SINGLE fp16 A.
// 128x128 tile, BK=64, 256 threads. Stage s at s*32768: A +0, B +16384.
// smem = 64KB. Single-barrier cp.async double-buffered pipeline.
// ---------------------------------------------------------------------------
#define GEMM2_SMEM 65536

__global__ __launch_bounds__(256, 2)
void gemm_f16s_kernel(const __half* __restrict__ A16,
                      const __half* __restrict__ B16,
                      float* __restrict__ C, int M, int N, int K, int ldc)
{
    extern __shared__ __align__(16) char smp[];
    const uint32_t sb = smem_u32(smp);

    const int tid = threadIdx.x;
    const int wid = tid >> 5;
    const int lane = tid & 31;
    const int m0 = blockIdx.x * 128;
    const int n0 = blockIdx.y * 128;
    const int wm = wid & 3;
    const int wn = wid >> 2;

    float acc[2][8][4];
#pragma unroll
    for (int mf = 0; mf < 2; mf++)
#pragma unroll
        for (int nf = 0; nf < 8; nf++)
#pragma unroll
            for (int q = 0; q < 4; q++) acc[mf][nf][q] = 0.f;

    const int KT = K >> 6;

    auto fill = [&](int buf, int kt) {
        const uint32_t base = sb + buf * 32768;
#pragma unroll
        for (int i = 0; i < 4; i++) {
            int u = tid + i * 256;
            int row = u >> 3, ch = u & 7;
            uint32_t off = sw128h(row, ch);
            size_t sA = (size_t)(m0 + row) * K + kt * 64 + ch * 8;
            size_t sB = (size_t)(n0 + row) * K + kt * 64 + ch * 8;
            CP_A16(base + off,         A16 + sA);
            CP_A16(base + 16384 + off, B16 + sB);
        }
        CP_COMMIT();
    };

    fill(0, 0);

    for (int kt = 0; kt < KT; kt++) {
        const int buf = kt & 1;
        CP_WAIT0();
        __syncthreads();
        if (kt + 1 < KT) fill(buf ^ 1, kt + 1);

        const uint32_t ab = sb + buf * 32768;
        const uint32_t bb = ab + 16384;
#pragma unroll
        for (int ks = 0; ks < 4; ks++) {
            uint32_t ah[2][4];
#pragma unroll
            for (int mf = 0; mf < 2; mf++) {
                int row = wm * 32 + mf * 16 + (lane & 15);
                int chunk = ks * 2 + (lane >> 4);
                ldsm_x4(ah[mf], ab + sw128h(row, chunk));
            }
            uint32_t bh[8][2];
#pragma unroll
            for (int np = 0; np < 4; np++) {
                int row = wn * 64 + np * 16 + ((lane >> 4) << 3) + (lane & 7);
                int chunk = ks * 2 + ((lane >> 3) & 1);
                uint32_t t[4];
                ldsm_x4(t, bb + sw128h(row, chunk));
                bh[np * 2][0] = t[0]; bh[np * 2][1] = t[1];
                bh[np * 2 + 1][0] = t[2]; bh[np * 2 + 1][1] = t[3];
            }
#pragma unroll
            for (int mf = 0; mf < 2; mf++)
#pragma unroll
                for (int nf = 0; nf < 8; nf++)
                    mma_f16(acc[mf][nf], ah[mf], bh[nf]);
        }
    }

#pragma unroll
    for (int mf = 0; mf < 2; mf++)
#pragma unroll
        for (int nf = 0; nf < 8; nf++) {
            int row = m0 + wm * 32 + mf * 16 + (lane >> 2);
            int col = n0 + wn * 64 + nf * 8 + (lane & 3) * 2;
            *(float2*)(C + (size_t)row * ldc + col) =
                make_float2(acc[mf][nf][0], acc[mf][nf][1]);
            *(float2*)(C + (size_t)(row + 8) * ldc + col) =
                make_float2(acc[mf][nf][2], acc[mf][nf][3]);
        }
}

// ---------------------------------------------------------------------------
// Flash attention (R12/R14 WIN core): software-pipelined, triple-buffered K/V,
// MUFU ex2 softmax. Q single fp16 frags in regs; P single fp16.
// Output: single fp16 (g_ath only).
// ---------------------------------------------------------------------------
#define ATT2_SMEM 98304

__global__ __launch_bounds__(128, 2)
void attn_reg_kernel(const __half* __restrict__ q_g,
                     const __half* __restrict__ k_g,
                     const __half* __restrict__ v_g, int T)
{
    extern __shared__ __align__(16) char smp[];
    const uint32_t sb = smem_u32(smp);

    const int tid = threadIdx.x;
    const int wid = tid >> 5;
    const int lane = tid & 31;
    const int bh = blockIdx.y;
    const int b  = bh >> 1;
    const int h  = bh & 1;

    const int bx = blockIdx.x;
    const int oo = bx & 3;
    const int qq = bx >> 2;
    const int pp_ = (qq & 1) ? (qq ^ 4) : qq;
    const int mt = (pp_ & 1) ? (4 * oo + (pp_ >> 1)) : (31 - 4 * oo - (pp_ >> 1));
    const int m0 = mt * 64;

    const size_t rb = (size_t)b * T;

    auto KB = [&](int bf) { return sb + bf * 16384; };
    auto VB = [&](int bf) { return sb + 49152 + bf * 16384; };

    auto fillKV = [&](int bf, int j) {
        const uint32_t kb = KB(bf);
        const uint32_t vb = VB(bf);
        const int n0v = j * 64;
#pragma unroll
        for (int i = 0; i < 8; i++) {
            int u = tid + i * 128;
            int row = u >> 4, ch = u & 15;
            uint32_t off = sw256(row, ch * 8);
            size_t src = (size_t)(rb + n0v + row) * 128 + ch * 8;
            CP_A16(kb + off, k_g + src);
            CP_A16(vb + off, v_g + src);
        }
        CP_COMMIT();
    };

    {
        const uint32_t qstage = VB(2);
#pragma unroll
        for (int i = 0; i < 8; i++) {
            int u = tid + i * 128;
            int row = u >> 4, ch = u & 15;
            uint32_t off = sw256(row, ch * 8);
            size_t src = (rb + m0 + row) * 256 + h * 128 + ch * 8;
            CP_A16(qstage + off, q_g + src);
        }
        const int n0v = 0;
#pragma unroll
        for (int i = 0; i < 8; i++) {
            int u = tid + i * 128;
            int row = u >> 4, ch = u & 15;
            uint32_t off = sw256(row, ch * 8);
            size_t src = (size_t)(rb + n0v + row) * 128 + ch * 8;
            CP_A16(KB(0) + off, k_g + src);
            CP_A16(VB(0) + off, v_g + src);
        }
        CP_COMMIT();
        CP_WAIT0();
        __syncthreads();
    }

    uint32_t qf[8][4];
#pragma unroll
    for (int ks = 0; ks < 8; ks++) {
        int row = wid * 16 + (lane & 15);
        int chunk = ks * 2 + (lane >> 4);
        ldsm_x4(qf[ks], VB(2) + sw256(row, chunk * 8));
    }

    if (mt >= 1) fillKV(1, 1);

    float mr0 = -1e30f, mr1 = -1e30f, lr0 = 0.f, lr1 = 0.f;
    float oacc[16][4];
#pragma unroll
    for (int nf = 0; nf < 16; nf++)
#pragma unroll
        for (int q = 0; q < 4; q++) oacc[nf][q] = 0.f;

    uint32_t pp[4][4];

    auto computeS = [&](uint32_t kb, float sacc[8][4]) {
#pragma unroll
        for (int nf = 0; nf < 8; nf++)
#pragma unroll
            for (int q = 0; q < 4; q++) sacc[nf][q] = 0.f;
#pragma unroll
        for (int ks = 0; ks < 8; ks++) {
#pragma unroll
            for (int ng = 0; ng < 4; ng++) {
                int row = ng * 16 + ((lane >> 4) << 3) + (lane & 7);
                int chunk = ks * 2 + ((lane >> 3) & 1);
                uint32_t t[4];
                ldsm_x4(t, kb + sw256(row, chunk * 8));
                uint32_t b0[2] = {t[0], t[1]}, b1[2] = {t[2], t[3]};
                mma_f16(sacc[ng * 2],     qf[ks], b0);
                mma_f16(sacc[ng * 2 + 1], qf[ks], b1);
            }
        }
    };

    auto softmax_pack = [&](float sacc[8][4], int jj) {
        if (jj == mt) {
            int grow0 = m0 + wid * 16 + (lane >> 2);
            int grow1 = grow0 + 8;
            int cbase = jj * 64 + (lane & 3) * 2;
#pragma unroll
            for (int nf = 0; nf < 8; nf++) {
                int c = cbase + nf * 8;
                if (c     > grow0) sacc[nf][0] = -1e30f;
                if (c + 1 > grow0) sacc[nf][1] = -1e30f;
                if (c     > grow1) sacc[nf][2] = -1e30f;
                if (c + 1 > grow1) sacc[nf][3] = -1e30f;
            }
        }
        float mx0 = -1e30f, mx1 = -1e30f;
#pragma unroll
        for (int nf = 0; nf < 8; nf++) {
            mx0 = fmaxf(mx0, fmaxf(sacc[nf][0], sacc[nf][1]));
            mx1 = fmaxf(mx1, fmaxf(sacc[nf][2], sacc[nf][3]));
        }
        mx0 = fmaxf(mx0, __shfl_xor_sync(0xffffffffu, mx0, 1));
        mx0 = fmaxf(mx0, __shfl_xor_sync(0xffffffffu, mx0, 2));
        mx1 = fmaxf(mx1, __shfl_xor_sync(0xffffffffu, mx1, 1));
        mx1 = fmaxf(mx1, __shfl_xor_sync(0xffffffffu, mx1, 2));

        float mn0 = fmaxf(mr0, mx0), mn1 = fmaxf(mr1, mx1);
        float corr0 = ex2(mr0 - mn0), corr1 = ex2(mr1 - mn1);
        mr0 = mn0; mr1 = mn1;

        float sum0 = 0.f, sum1 = 0.f;
#pragma unroll
        for (int nf = 0; nf < 8; nf++) {
            sacc[nf][0] = ex2(sacc[nf][0] - mn0);
            sacc[nf][1] = ex2(sacc[nf][1] - mn0);
            sacc[nf][2] = ex2(sacc[nf][2] - mn1);
            sacc[nf][3] = ex2(sacc[nf][3] - mn1);
            sum0 += sacc[nf][0] + sacc[nf][1];
            sum1 += sacc[nf][2] + sacc[nf][3];
        }
        sum0 += __shfl_xor_sync(0xffffffffu, sum0, 1);
        sum0 += __shfl_xor_sync(0xffffffffu, sum0, 2);
        sum1 += __shfl_xor_sync(0xffffffffu, sum1, 1);
        sum1 += __shfl_xor_sync(0xffffffffu, sum1, 2);
        lr0 = lr0 * corr0 + sum0;
        lr1 = lr1 * corr1 + sum1;

        if (__any_sync(0xffffffffu, (corr0 < 1.0f) | (corr1 < 1.0f))) {
#pragma unroll
            for (int nf = 0; nf < 16; nf++) {
                oacc[nf][0] *= corr0; oacc[nf][1] *= corr0;
                oacc[nf][2] *= corr1; oacc[nf][3] *= corr1;
            }
        }
#pragma unroll
        for (int kc = 0; kc < 4; kc++) {
            pp[kc][0] = packh2(sacc[2 * kc][0],     sacc[2 * kc][1]);
            pp[kc][1] = packh2(sacc[2 * kc][2],     sacc[2 * kc][3]);
            pp[kc][2] = packh2(sacc[2 * kc + 1][0], sacc[2 * kc + 1][1]);
            pp[kc][3] = packh2(sacc[2 * kc + 1][2], sacc[2 * kc + 1][3]);
        }
    };

    auto computePV = [&](uint32_t vb) {
#pragma unroll
        for (int ks2 = 0; ks2 < 4; ks2++) {
            int vrow = ks2 * 16 + (lane & 15);
#pragma unroll
            for (int g = 0; g < 8; g++) {
                int chunk = g * 2 + (lane >> 4);
                uint32_t vh[4];
                ldsm_x4_t(vh, vb + sw256(vrow, chunk * 8));
                uint32_t vh0[2] = {vh[0], vh[1]}, vh1[2] = {vh[2], vh[3]};
                mma_f16(oacc[g * 2],     pp[ks2], vh0);
                mma_f16(oacc[g * 2 + 1], pp[ks2], vh1);
            }
        }
    };

    {
        float sacc[8][4];
        computeS(KB(0), sacc);
        softmax_pack(sacc, 0);
    }

    for (int j = 0; j < mt; j++) {
        const int bufc = j % 3;
        const int bufn = (j + 1) % 3;

        CP_WAIT0();
        __syncthreads();
        if (j + 2 <= mt) fillKV((j + 2) % 3, j + 2);

        float sacc[8][4];
        computeS(KB(bufn), sacc);
        computePV(VB(bufc));

        softmax_pack(sacc, j + 1);
    }

    computePV(VB(mt % 3));

    // ---- epilogue: normalize + single fp16 store ----
    float inv0 = 1.0f / lr0;
    float inv1 = 1.0f / lr1;
    size_t row0 = rb + m0 + wid * 16 + (lane >> 2);
#pragma unroll
    for (int nf = 0; nf < 16; nf++) {
        int col = h * 128 + nf * 8 + (lane & 3) * 2;
        *(uint32_t*)(g_ath + row0 * 256 + col) =
            packh2(oacc[nf][0] * inv0, oacc[nf][1] * inv0);
        *(uint32_t*)(g_ath + (row0 + 8) * 256 + col) =
            packh2(oacc[nf][2] * inv1, oacc[nf][3] * inv1);
    }
}

// ---------------------------------------------------------------------------
extern "C" void kernel_launch(void* const* d_in, const int* in_sizes, int n_in,
                              void* d_out, int out_size)
{
    const float* x  = (const float*)d_in[0];
    const float* Wq = (const float*)d_in[1];
    const float* Wk = (const float*)d_in[2];
    const float* Wv = (const float*)d_in[3];
    const float* Wo = (const float*)d_in[4];

    const int BT = in_sizes[0] / DIM;  // 8192
    const int T  = T_SEQ;
    const int B  = BT / T;

    __half *q16, *k16, *v16, *ath, *w16, *wo16;
    cudaGetSymbolAddress((void**)&q16,  g_q16);
    cudaGetSymbolAddress((void**)&k16,  g_k16);
    cudaGetSymbolAddress((void**)&v16,  g_v16);
    cudaGetSymbolAddress((void**)&ath,  g_ath);
    cudaGetSymbolAddress((void**)&w16,  g_w16);
    cudaGetSymbolAddress((void**)&wo16, g_wo16);

    cudaFuncSetAttribute(gemm_x_kernel,
                         cudaFuncAttributeMaxDynamicSharedMemorySize, GEMM_SMEM);
    cudaFuncSetAttribute(gemm_f16s_kernel,
                         cudaFuncAttributeMaxDynamicSharedMemorySize, GEMM2_SMEM);
    cudaFuncSetAttribute(attn_reg_kernel,
                         cudaFuncAttributeMaxDynamicSharedMemorySize, ATT2_SMEM);

    // 1) prep (weights + trig)
    {
        int wt = 512 * DIM / 4 + DIM * 256 / 4 + T_SEQ * 64;
        prep_kernel<<<(wt + 255) / 256, 256>>>(Wq, Wk, Wv, Wo);
    }

    // 2) fused QKV projection (inline fp32->fp16 split) + rope epilogue
    {
        dim3 grid(BT / 128, 512 / 128);
        gemm_x_kernel<<<grid, 256, GEMM_SMEM>>>(x, w16, BT, 512, DIM);
    }

    // 3) flash attention
    {
        dim3 grid(T / 64, B * NKV);
        attn_reg_kernel<<<grid, 128, ATT2_SMEM>>>(q16, k16, v16, T);
    }

    // 4) output projection (single-fp16 A)
    {
        dim3 grid(BT / 128, DIM / 128);
        gemm_f16s_kernel<<<grid, 256, GEMM2_SMEM>>>(ath, wo16, (float*)d_out,
                                                    BT, DIM, 256, DIM);
    }
}

// round 16
// speedup vs baseline: 1.4240x; 1.2087x over previous
#include <cuda_runtime.h>
#include <cuda_bf16.h>
#include <cuda_fp16.h>
#include <math.h>
#include <float.h>
#include <stdint.h>

// Problem constants (fixed by reference setup_inputs)
#define DIM   1024
#define HS    128
#define NKV   2
#define T_SEQ 2048
#define BT_MAX 8192   // B*T = 4*2048

// ---------------- scratch (static device allocations; no cudaMalloc) -------
__device__ __half  g_q16  [BT_MAX * 256];   // rope'd+scaled Q, single fp16
__device__ __half  g_k16  [BT_MAX * 128];   // rope'd K, single fp16
__device__ __half  g_v16  [BT_MAX * 128];   // V, single fp16
__device__ __half  g_ath  [BT_MAX * 256];   // attention out, single fp16
__device__ __half  g_w16  [512 * DIM];      // Wcat single fp16
__device__ __half  g_wo16 [DIM * 256];      // Wo single fp16
__device__ float2  g_trig [T_SEQ * 64];     // (cos, sin) per (t, pair)

// ============================================================================
// helpers
// ============================================================================
__device__ __forceinline__ uint32_t smem_u32(const void* p) {
    uint32_t a;
    asm("{ .reg .u64 t; cvta.to.shared.u64 t, %1; cvt.u32.u64 %0, t; }"
        : "=r"(a) : "l"(p));
    return a;
}

__device__ __forceinline__ void mma_f16(float c[4], const uint32_t a[4],
                                        const uint32_t b[2]) {
    asm volatile(
        "mma.sync.aligned.m16n8k16.row.col.f32.f16.f16.f32 "
        "{%0,%1,%2,%3}, {%4,%5,%6,%7}, {%8,%9}, {%0,%1,%2,%3};"
        : "+f"(c[0]), "+f"(c[1]), "+f"(c[2]), "+f"(c[3])
        : "r"(a[0]), "r"(a[1]), "r"(a[2]), "r"(a[3]), "r"(b[0]), "r"(b[1]));
}

__device__ __forceinline__ void ldsm_x4(uint32_t r[4], uint32_t addr) {
    asm volatile("ldmatrix.sync.aligned.m8n8.x4.shared.b16 {%0,%1,%2,%3}, [%4];"
                 : "=r"(r[0]), "=r"(r[1]), "=r"(r[2]), "=r"(r[3]) : "r"(addr));
}
__device__ __forceinline__ void ldsm_x4_t(uint32_t r[4], uint32_t addr) {
    asm volatile("ldmatrix.sync.aligned.m8n8.x4.trans.shared.b16 {%0,%1,%2,%3}, [%4];"
                 : "=r"(r[0]), "=r"(r[1]), "=r"(r[2]), "=r"(r[3]) : "r"(addr));
}

#define CP_A16(dst, src) \
    asm volatile("cp.async.cg.shared.global [%0], [%1], 16;" \
                 :: "r"(dst), "l"(src) : "memory")
#define CP_COMMIT() asm volatile("cp.async.commit_group;" ::: "memory")
#define CP_WAIT0()  asm volatile("cp.async.wait_group 0;" ::: "memory")

__device__ __forceinline__ uint32_t packh2(float x, float y) {
    __half2 h = __float22half2_rn(make_float2(x, y));
    return *(uint32_t*)&h;
}

// MUFU exp2: 1 instruction/value. ex2(-huge) -> 0 exactly.
__device__ __forceinline__ float ex2(float y) {
    float r;
    asm("ex2.approx.ftz.f32 %0, %1;" : "=f"(r) : "f"(y));
    return r;
}

// Swizzle for 128-col 16-bit tiles (256B rows), 16B chunks (attention)
__device__ __forceinline__ uint32_t sw256(int row, int col) {
    int chunk = col >> 3;
    return (uint32_t)(row * 256 + (((chunk ^ (row & 7)) << 4) | ((col & 7) << 1)));
}
// Swizzle for 64-col fp16 tiles (128B rows), 8 chunks of 16B (GEMM)
__device__ __forceinline__ uint32_t sw128h(int row, int chunk) {
    return (uint32_t)(row * 128 + ((chunk ^ (row & 7)) << 4));
}

// ---------------------------------------------------------------------------
// Weight concat + fp16 convert + trig table (one launch)
// ---------------------------------------------------------------------------
__global__ void prep_kernel(const float* __restrict__ Wq,
                            const float* __restrict__ Wk,
                            const float* __restrict__ Wv,
                            const float* __restrict__ Wo)
{
    int i = blockIdx.x * blockDim.x + threadIdx.x;
    const int WCAT4 = 512 * DIM / 4;
    const int WO4   = DIM * 256 / 4;
    const int TRIG  = T_SEQ * 64;
    if (i < WCAT4) {
        int row = i >> 8;
        float4 v;
        if (row < 256)       v = ((const float4*)Wq)[i];
        else if (row < 384)  v = ((const float4*)Wk)[i - 256 * 256];
        else                 v = ((const float4*)Wv)[i - 384 * 256];
        uint2 w;
        w.x = packh2(v.x, v.y);
        w.y = packh2(v.z, v.w);
        *(uint2*)(g_w16 + i * 4) = w;
    } else if (i < WCAT4 + WO4) {
        int j = i - WCAT4;
        float4 v = ((const float4*)Wo)[j];
        uint2 w;
        w.x = packh2(v.x, v.y);
        w.y = packh2(v.z, v.w);
        *(uint2*)(g_wo16 + j * 4) = w;
    } else if (i < WCAT4 + WO4 + TRIG) {
        int j = i - WCAT4 - WO4;
        int t = j >> 6, k = j & 63;
        float theta = exp2f(-(float)k * (13.287712379549449f / 32.0f));
        float s, c;
        sincosf((float)t * theta, &s, &c);
        g_trig[j] = make_float2(c, s);
    }
}

// ---------------------------------------------------------------------------
// rope epilogue store (GEMM1)
// ---------------------------------------------------------------------------
__device__ __forceinline__ void rope_epi_store(int r, int c, float x0, float x1)
{
    const float qscale = 0.08838834764831845f * 1.4426950408889634f;
    int t = r & (T_SEQ - 1);
    if (c < 384) {
        int i = (c & 127) >> 1;
        float2 cs = g_trig[t * 64 + i];
        float y0 = x0 * cs.x - x1 * cs.y;
        float y1 = x1 * cs.x + x0 * cs.y;
        if (c < 256) {
            y0 *= qscale; y1 *= qscale;
            *(uint32_t*)(g_q16 + (size_t)r * 256 + c) = packh2(y0, y1);
        } else {
            *(uint32_t*)(g_k16 + (size_t)r * 128 + (c - 256)) = packh2(y0, y1);
        }
    } else {
        *(uint32_t*)(g_v16 + (size_t)r * 128 + (c - 384)) = packh2(x0, x1);
    }
}

// ---------------------------------------------------------------------------
// GEMM1: qkv = x (fp32 -> single fp16 inline) * Wcat16^T, rope epilogue.
// 128x128 CTA tile, BK=64, 256 threads. A: LDG fp32 -> cvt -> STS (two
// 16-reg batches interleaved with compute halves). B: cp.async double-buffer.
// Stage s at s*32768: A +0, B +16384. smem = 64KB.
// ---------------------------------------------------------------------------
#define GEMM_SMEM 65536

__global__ __launch_bounds__(256, 2)
void gemm_x_kernel(const float* __restrict__ X,
                   const __half* __restrict__ B16,
                   int M, int N, int K)
{
    extern __shared__ __align__(16) char smp[];
    const uint32_t sb = smem_u32(smp);

    const int tid = threadIdx.x;
    const int wid = tid >> 5;
    const int lane = tid & 31;
    const int m0 = blockIdx.x * 128;
    const int n0 = blockIdx.y * 128;
    const int wm = wid & 3;
    const int wn = wid >> 2;

    float acc[2][8][4];
#pragma unroll
    for (int mf = 0; mf < 2; mf++)
#pragma unroll
        for (int nf = 0; nf < 8; nf++)
#pragma unroll
            for (int q = 0; q < 4; q++) acc[mf][nf][q] = 0.f;

    const int KT = K >> 6;    // 16

    auto fillB = [&](int buf, int kt) {
        const uint32_t bbase = sb + buf * 32768 + 16384;
#pragma unroll
        for (int i = 0; i < 4; i++) {
            int u = tid + i * 256;
            int row = u >> 3, ch = u & 7;
            CP_A16(bbase + sw128h(row, ch),
                   B16 + (size_t)(n0 + row) * K + kt * 64 + ch * 8);
        }
        CP_COMMIT();
    };

    // A LDG batch: 4 float4 per thread (batch bsel in {0,1})
    auto ldgA = [&](int kt, int bsel, float4 vr[4]) {
#pragma unroll
        for (int i = 0; i < 4; i++) {
            int u = tid + (bsel * 4 + i) * 256;    // 0..2047
            int row = u >> 4, q4 = u & 15;
            vr[i] = *(const float4*)(X + (size_t)(m0 + row) * K + kt * 64 + q4 * 4);
        }
    };
    // A convert (single fp16) + STS batch
    auto stsA = [&](int buf, int bsel, const float4 vr[4]) {
#pragma unroll
        for (int i = 0; i < 4; i++) {
            int u = tid + (bsel * 4 + i) * 256;
            int row = u >> 4, q4 = u & 15;
            uint32_t off = sw128h(row, q4 >> 1) + (q4 & 1) * 8;
            *(uint2*)(smp + (off + buf * 32768)) =
                make_uint2(packh2(vr[i].x, vr[i].y), packh2(vr[i].z, vr[i].w));
        }
    };

    {
        float4 v0[4], v1[4];
        ldgA(0, 0, v0);
        ldgA(0, 1, v1);
        fillB(0, 0);
        stsA(0, 0, v0);
        stsA(0, 1, v1);
        CP_WAIT0();
        __syncthreads();
    }

    for (int kt = 0; kt < KT; kt++) {
        const int buf = kt & 1;
        const bool pre = (kt + 1 < KT);

        float4 vr[4];
        if (pre) {
            fillB(buf ^ 1, kt + 1);
            ldgA(kt + 1, 0, vr);
        }

        const uint32_t ab = sb + buf * 32768;
        const uint32_t bb = ab + 16384;

        // ---- compute half 1 (ks = 0,1) ----
#pragma unroll
        for (int ks = 0; ks < 2; ks++) {
            uint32_t ah[2][4];
#pragma unroll
            for (int mf = 0; mf < 2; mf++) {
                int row = wm * 32 + mf * 16 + (lane & 15);
                int chunk = ks * 2 + (lane >> 4);
                ldsm_x4(ah[mf], ab + sw128h(row, chunk));
            }
            uint32_t bh[8][2];
#pragma unroll
            for (int np = 0; np < 4; np++) {
                int row = wn * 64 + np * 16 + ((lane >> 4) << 3) + (lane & 7);
                int chunk = ks * 2 + ((lane >> 3) & 1);
                uint32_t t[4];
                ldsm_x4(t, bb + sw128h(row, chunk));
                bh[np * 2][0] = t[0]; bh[np * 2][1] = t[1];
                bh[np * 2 + 1][0] = t[2]; bh[np * 2 + 1][1] = t[3];
            }
#pragma unroll
            for (int mf = 0; mf < 2; mf++)
#pragma unroll
                for (int nf = 0; nf < 8; nf++)
                    mma_f16(acc[mf][nf], ah[mf], bh[nf]);
        }

        if (pre) {
            stsA(buf ^ 1, 0, vr);
            ldgA(kt + 1, 1, vr);
        }

        // ---- compute half 2 (ks = 2,3) ----
#pragma unroll
        for (int ks = 2; ks < 4; ks++) {
            uint32_t ah[2][4];
#pragma unroll
            for (int mf = 0; mf < 2; mf++) {
                int row = wm * 32 + mf * 16 + (lane & 15);
                int chunk = ks * 2 + (lane >> 4);
                ldsm_x4(ah[mf], ab + sw128h(row, chunk));
            }
            uint32_t bh[8][2];
#pragma unroll
            for (int np = 0; np < 4; np++) {
                int row = wn * 64 + np * 16 + ((lane >> 4) << 3) + (lane & 7);
                int chunk = ks * 2 + ((lane >> 3) & 1);
                uint32_t t[4];
                ldsm_x4(t, bb + sw128h(row, chunk));
                bh[np * 2][0] = t[0]; bh[np * 2][1] = t[1];
                bh[np * 2 + 1][0] = t[2]; bh[np * 2 + 1][1] = t[3];
            }
#pragma unroll
            for (int mf = 0; mf < 2; mf++)
#pragma unroll
                for (int nf = 0; nf < 8; nf++)
                    mma_f16(acc[mf][nf], ah[mf], bh[nf]);
        }

        if (pre) stsA(buf ^ 1, 1, vr);

        if (pre) {
            CP_WAIT0();
        }
        __syncthreads();
    }

#pragma unroll
    for (int mf = 0; mf < 2; mf++)
#pragma unroll
        for (int nf = 0; nf < 8; nf++) {
            int row = m0 + wm * 32 + mf * 16 + (lane >> 2);
            int col = n0 + wn * 64 + nf * 8 + (lane & 3) * 2;
            rope_epi_store(row,     col, acc[mf][nf][0], acc[mf][nf][1]);
            rope_epi_store(row + 8, col, acc[mf][nf][2], acc[mf][nf][3]);
        }
}

// ---------------------------------------------------------------------------
// GEMM2 (frozen R15 WIN): out = A16 * Wo16^T, fp32 C. Single fp16 A.
// ---------------------------------------------------------------------------
#define GEMM2_SMEM 65536

__global__ __launch_bounds__(256, 2)
void gemm_f16s_kernel(const __half* __restrict__ A16,
                      const __half* __restrict__ B16,
                      float* __restrict__ C, int M, int N, int K, int ldc)
{
    extern __shared__ __align__(16) char smp[];
    const uint32_t sb = smem_u32(smp);

    const int tid = threadIdx.x;
    const int wid = tid >> 5;
    const int lane = tid & 31;
    const int m0 = blockIdx.x * 128;
    const int n0 = blockIdx.y * 128;
    const int wm = wid & 3;
    const int wn = wid >> 2;

    float acc[2][8][4];
#pragma unroll
    for (int mf = 0; mf < 2; mf++)
#pragma unroll
        for (int nf = 0; nf < 8; nf++)
#pragma unroll
            for (int q = 0; q < 4; q++) acc[mf][nf][q] = 0.f;

    const int KT = K >> 6;

    auto fill = [&](int buf, int kt) {
        const uint32_t base = sb + buf * 32768;
#pragma unroll
        for (int i = 0; i < 4; i++) {
            int u = tid + i * 256;
            int row = u >> 3, ch = u & 7;
            uint32_t off = sw128h(row, ch);
            size_t sA = (size_t)(m0 + row) * K + kt * 64 + ch * 8;
            size_t sB = (size_t)(n0 + row) * K + kt * 64 + ch * 8;
            CP_A16(base + off,         A16 + sA);
            CP_A16(base + 16384 + off, B16 + sB);
        }
        CP_COMMIT();
    };

    fill(0, 0);

    for (int kt = 0; kt < KT; kt++) {
        const int buf = kt & 1;
        CP_WAIT0();
        __syncthreads();
        if (kt + 1 < KT) fill(buf ^ 1, kt + 1);

        const uint32_t ab = sb + buf * 32768;
        const uint32_t bb = ab + 16384;
#pragma unroll
        for (int ks = 0; ks < 4; ks++) {
            uint32_t ah[2][4];
#pragma unroll
            for (int mf = 0; mf < 2; mf++) {
                int row = wm * 32 + mf * 16 + (lane & 15);
                int chunk = ks * 2 + (lane >> 4);
                ldsm_x4(ah[mf], ab + sw128h(row, chunk));
            }
            uint32_t bh[8][2];
#pragma unroll
            for (int np = 0; np < 4; np++) {
                int row = wn * 64 + np * 16 + ((lane >> 4) << 3) + (lane & 7);
                int chunk = ks * 2 + ((lane >> 3) & 1);
                uint32_t t[4];
                ldsm_x4(t, bb + sw128h(row, chunk));
                bh[np * 2][0] = t[0]; bh[np * 2][1] = t[1];
                bh[np * 2 + 1][0] = t[2]; bh[np * 2 + 1][1] = t[3];
            }
#pragma unroll
            for (int mf = 0; mf < 2; mf++)
#pragma unroll
                for (int nf = 0; nf < 8; nf++)
                    mma_f16(acc[mf][nf], ah[mf], bh[nf]);
        }
    }

#pragma unroll
    for (int mf = 0; mf < 2; mf++)
#pragma unroll
        for (int nf = 0; nf < 8; nf++) {
            int row = m0 + wm * 32 + mf * 16 + (lane >> 2);
            int col = n0 + wn * 64 + nf * 8 + (lane & 3) * 2;
            *(float2*)(C + (size_t)row * ldc + col) =
                make_float2(acc[mf][nf][0], acc[mf][nf][1]);
            *(float2*)(C + (size_t)(row + 8) * ldc + col) =
                make_float2(acc[mf][nf][2], acc[mf][nf][3]);
        }
}

// ---------------------------------------------------------------------------
// Flash attention (frozen R15 WIN): software-pipelined, triple-buffered K/V,
// MUFU ex2 softmax. Q/P single fp16. Output: single fp16.
// ---------------------------------------------------------------------------
#define ATT2_SMEM 98304

__global__ __launch_bounds__(128, 2)
void attn_reg_kernel(const __half* __restrict__ q_g,
                     const __half* __restrict__ k_g,
                     const __half* __restrict__ v_g, int T)
{
    extern __shared__ __align__(16) char smp[];
    const uint32_t sb = smem_u32(smp);

    const int tid = threadIdx.x;
    const int wid = tid >> 5;
    const int lane = tid & 31;
    const int bh = blockIdx.y;
    const int b  = bh >> 1;
    const int h  = bh & 1;

    const int bx = blockIdx.x;
    const int oo = bx & 3;
    const int qq = bx >> 2;
    const int pp_ = (qq & 1) ? (qq ^ 4) : qq;
    const int mt = (pp_ & 1) ? (4 * oo + (pp_ >> 1)) : (31 - 4 * oo - (pp_ >> 1));
    const int m0 = mt * 64;

    const size_t rb = (size_t)b * T;

    auto KB = [&](int bf) { return sb + bf * 16384; };
    auto VB = [&](int bf) { return sb + 49152 + bf * 16384; };

    auto fillKV = [&](int bf, int j) {
        const uint32_t kb = KB(bf);
        const uint32_t vb = VB(bf);
        const int n0v = j * 64;
#pragma unroll
        for (int i = 0; i < 8; i++) {
            int u = tid + i * 128;
            int row = u >> 4, ch = u & 15;
            uint32_t off = sw256(row, ch * 8);
            size_t src = (size_t)(rb + n0v + row) * 128 + ch * 8;
            CP_A16(kb + off, k_g + src);
            CP_A16(vb + off, v_g + src);
        }
        CP_COMMIT();
    };

    {
        const uint32_t qstage = VB(2);
#pragma unroll
        for (int i = 0; i < 8; i++) {
            int u = tid + i * 128;
            int row = u >> 4, ch = u & 15;
            uint32_t off = sw256(row, ch * 8);
            size_t src = (rb + m0 + row) * 256 + h * 128 + ch * 8;
            CP_A16(qstage + off, q_g + src);
        }
        const int n0v = 0;
#pragma unroll
        for (int i = 0; i < 8; i++) {
            int u = tid + i * 128;
            int row = u >> 4, ch = u & 15;
            uint32_t off = sw256(row, ch * 8);
            size_t src = (size_t)(rb + n0v + row) * 128 + ch * 8;
            CP_A16(KB(0) + off, k_g + src);
            CP_A16(VB(0) + off, v_g + src);
        }
        CP_COMMIT();
        CP_WAIT0();
        __syncthreads();
    }

    uint32_t qf[8][4];
#pragma unroll
    for (int ks = 0; ks < 8; ks++) {
        int row = wid * 16 + (lane & 15);
        int chunk = ks * 2 + (lane >> 4);
        ldsm_x4(qf[ks], VB(2) + sw256(row, chunk * 8));
    }

    if (mt >= 1) fillKV(1, 1);

    float mr0 = -1e30f, mr1 = -1e30f, lr0 = 0.f, lr1 = 0.f;
    float oacc[16][4];
#pragma unroll
    for (int nf = 0; nf < 16; nf++)
#pragma unroll
        for (int q = 0; q < 4; q++) oacc[nf][q] = 0.f;

    uint32_t pp[4][4];

    auto computeS = [&](uint32_t kb, float sacc[8][4]) {
#pragma unroll
        for (int nf = 0; nf < 8; nf++)
#pragma unroll
            for (int q = 0; q < 4; q++) sacc[nf][q] = 0.f;
#pragma unroll
        for (int ks = 0; ks < 8; ks++) {
#pragma unroll
            for (int ng = 0; ng < 4; ng++) {
                int row = ng * 16 + ((lane >> 4) << 3) + (lane & 7);
                int chunk = ks * 2 + ((lane >> 3) & 1);
                uint32_t t[4];
                ldsm_x4(t, kb + sw256(row, chunk * 8));
                uint32_t b0[2] = {t[0], t[1]}, b1[2] = {t[2], t[3]};
                mma_f16(sacc[ng * 2],     qf[ks], b0);
                mma_f16(sacc[ng * 2 + 1], qf[ks], b1);
            }
        }
    };

    auto softmax_pack = [&](float sacc[8][4], int jj) {
        if (jj == mt) {
            int grow0 = m0 + wid * 16 + (lane >> 2);
            int grow1 = grow0 + 8;
            int cbase = jj * 64 + (lane & 3) * 2;
#pragma unroll
            for (int nf = 0; nf < 8; nf++) {
                int c = cbase + nf * 8;
                if (c     > grow0) sacc[nf][0] = -1e30f;
                if (c + 1 > grow0) sacc[nf][1] = -1e30f;
                if (c     > grow1) sacc[nf][2] = -1e30f;
                if (c + 1 > grow1) sacc[nf][3] = -1e30f;
            }
        }
        float mx0 = -1e30f, mx1 = -1e30f;
#pragma unroll
        for (int nf = 0; nf < 8; nf++) {
            mx0 = fmaxf(mx0, fmaxf(sacc[nf][0], sacc[nf][1]));
            mx1 = fmaxf(mx1, fmaxf(sacc[nf][2], sacc[nf][3]));
        }
        mx0 = fmaxf(mx0, __shfl_xor_sync(0xffffffffu, mx0, 1));
        mx0 = fmaxf(mx0, __shfl_xor_sync(0xffffffffu, mx0, 2));
        mx1 = fmaxf(mx1, __shfl_xor_sync(0xffffffffu, mx1, 1));
        mx1 = fmaxf(mx1, __shfl_xor_sync(0xffffffffu, mx1, 2));

        float mn0 = fmaxf(mr0, mx0), mn1 = fmaxf(mr1, mx1);
        float corr0 = ex2(mr0 - mn0), corr1 = ex2(mr1 - mn1);
        mr0 = mn0; mr1 = mn1;

        float sum0 = 0.f, sum1 = 0.f;
#pragma unroll
        for (int nf = 0; nf < 8; nf++) {
            sacc[nf][0] = ex2(sacc[nf][0] - mn0);
            sacc[nf][1] = ex2(sacc[nf][1] - mn0);
            sacc[nf][2] = ex2(sacc[nf][2] - mn1);
            sacc[nf][3] = ex2(sacc[nf][3] - mn1);
            sum0 += sacc[nf][0] + sacc[nf][1];
            sum1 += sacc[nf][2] + sacc[nf][3];
        }
        sum0 += __shfl_xor_sync(0xffffffffu, sum0, 1);
        sum0 += __shfl_xor_sync(0xffffffffu, sum0, 2);
        sum1 += __shfl_xor_sync(0xffffffffu, sum1, 1);
        sum1 += __shfl_xor_sync(0xffffffffu, sum1, 2);
        lr0 = lr0 * corr0 + sum0;
        lr1 = lr1 * corr1 + sum1;

        if (__any_sync(0xffffffffu, (corr0 < 1.0f) | (corr1 < 1.0f))) {
#pragma unroll
            for (int nf = 0; nf < 16; nf++) {
                oacc[nf][0] *= corr0; oacc[nf][1] *= corr0;
                oacc[nf][2] *= corr1; oacc[nf][3] *= corr1;
            }
        }
#pragma unroll
        for (int kc = 0; kc < 4; kc++) {
            pp[kc][0] = packh2(sacc[2 * kc][0],     sacc[2 * kc][1]);
            pp[kc][1] = packh2(sacc[2 * kc][2],     sacc[2 * kc][3]);
            pp[kc][2] = packh2(sacc[2 * kc + 1][0], sacc[2 * kc + 1][1]);
            pp[kc][3] = packh2(sacc[2 * kc + 1][2], sacc[2 * kc + 1][3]);
        }
    };

    auto computePV = [&](uint32_t vb) {
#pragma unroll
        for (int ks2 = 0; ks2 < 4; ks2++) {
            int vrow = ks2 * 16 + (lane & 15);
#pragma unroll
            for (int g = 0; g < 8; g++) {
                int chunk = g * 2 + (lane >> 4);
                uint32_t vh[4];
                ldsm_x4_t(vh, vb + sw256(vrow, chunk * 8));
                uint32_t vh0[2] = {vh[0], vh[1]}, vh1[2] = {vh[2], vh[3]};
                mma_f16(oacc[g * 2],     pp[ks2], vh0);
                mma_f16(oacc[g * 2 + 1], pp[ks2], vh1);
            }
        }
    };

    {
        float sacc[8][4];
        computeS(KB(0), sacc);
        softmax_pack(sacc, 0);
    }

    for (int j = 0; j < mt; j++) {
        const int bufc = j % 3;
        const int bufn = (j + 1) % 3;

        CP_WAIT0();
        __syncthreads();
        if (j + 2 <= mt) fillKV((j + 2) % 3, j + 2);

        float sacc[8][4];
        computeS(KB(bufn), sacc);
        computePV(VB(bufc));

        softmax_pack(sacc, j + 1);
    }

    computePV(VB(mt % 3));

    float inv0 = 1.0f / lr0;
    float inv1 = 1.0f / lr1;
    size_t row0 = rb + m0 + wid * 16 + (lane >> 2);
#pragma unroll
    for (int nf = 0; nf < 16; nf++) {
        int col = h * 128 + nf * 8 + (lane & 3) * 2;
        *(uint32_t*)(g_ath + row0 * 256 + col) =
            packh2(oacc[nf][0] * inv0, oacc[nf][1] * inv0);
        *(uint32_t*)(g_ath + (row0 + 8) * 256 + col) =
            packh2(oacc[nf][2] * inv1, oacc[nf][3] * inv1);
    }
}

// ---------------------------------------------------------------------------
extern "C" void kernel_launch(void* const* d_in, const int* in_sizes, int n_in,
                              void* d_out, int out_size)
{
    const float* x  = (const float*)d_in[0];
    const float* Wq = (const float*)d_in[1];
    const float* Wk = (const float*)d_in[2];
    const float* Wv = (const float*)d_in[3];
    const float* Wo = (const float*)d_in[4];

    const int BT = in_sizes[0] / DIM;  // 8192
    const int T  = T_SEQ;
    const int B  = BT / T;

    __half *q16, *k16, *v16, *ath, *w16, *wo16;
    cudaGetSymbolAddress((void**)&q16,  g_q16);
    cudaGetSymbolAddress((void**)&k16,  g_k16);
    cudaGetSymbolAddress((void**)&v16,  g_v16);
    cudaGetSymbolAddress((void**)&ath,  g_ath);
    cudaGetSymbolAddress((void**)&w16,  g_w16);
    cudaGetSymbolAddress((void**)&wo16, g_wo16);

    cudaFuncSetAttribute(gemm_x_kernel,
                         cudaFuncAttributeMaxDynamicSharedMemorySize, GEMM_SMEM);
    cudaFuncSetAttribute(gemm_f16s_kernel,
                         cudaFuncAttributeMaxDynamicSharedMemorySize, GEMM2_SMEM);
    cudaFuncSetAttribute(attn_reg_kernel,
                         cudaFuncAttributeMaxDynamicSharedMemorySize, ATT2_SMEM);

    // 1) prep (weights + trig)
    {
        int wt = 512 * DIM / 4 + DIM * 256 / 4 + T_SEQ * 64;
        prep_kernel<<<(wt + 255) / 256, 256>>>(Wq, Wk, Wv, Wo);
    }

    // 2) fused QKV projection (x -> single fp16 inline) + rope epilogue
    {
        dim3 grid(BT / 128, 512 / 128);
        gemm_x_kernel<<<grid, 256, GEMM_SMEM>>>(x, w16, BT, 512, DIM);
    }

    // 3) flash attention
    {
        dim3 grid(T / 64, B * NKV);
        attn_reg_kernel<<<grid, 128, ATT2_SMEM>>>(q16, k16, v16, T);
    }

    // 4) output projection (single-fp16 A)
    {
        dim3 grid(BT / 128, DIM / 128);
        gemm_f16s_kernel<<<grid, 256, GEMM2_SMEM>>>(ath, wo16, (float*)d_out,
                                                    BT, DIM, 256, DIM);
    }
}

// round 17
// speedup vs baseline: 1.4997x; 1.0532x over previous
#include <cuda_runtime.h>
#include <cuda_bf16.h>
#include <cuda_fp16.h>
#include <math.h>
#include <float.h>
#include <stdint.h>

// Problem constants (fixed by reference setup_inputs)
#define DIM   1024
#define HS    128
#define NKV   2
#define T_SEQ 2048
#define BT_MAX 8192   // B*T = 4*2048

// ---------------- scratch (static device allocations; no cudaMalloc) -------
__device__ __half  g_q16  [BT_MAX * 256];   // rope'd+scaled Q, single fp16
__device__ __half  g_k16  [BT_MAX * 128];   // rope'd K, single fp16
__device__ __half  g_v16  [BT_MAX * 128];   // V, single fp16
__device__ __half  g_ath  [BT_MAX * 256];   // attention out, single fp16
__device__ __half  g_w16  [512 * DIM];      // Wcat single fp16
__device__ __half  g_wo16 [DIM * 256];      // Wo single fp16
__device__ float2  g_trig [T_SEQ * 64];     // (cos, sin) per (t, pair)
__device__ float   g_po   [2 * BT_MAX * 256];  // split-KV partial O (fp32)
__device__ float   g_pm   [2 * BT_MAX * 2];    // partial m (log2 domain)
__device__ float   g_pl   [2 * BT_MAX * 2];    // partial l

// ============================================================================
// helpers
// ============================================================================
__device__ __forceinline__ uint32_t smem_u32(const void* p) {
    uint32_t a;
    asm("{ .reg .u64 t; cvta.to.shared.u64 t, %1; cvt.u32.u64 %0, t; }"
        : "=r"(a) : "l"(p));
    return a;
}

__device__ __forceinline__ void mma_f16(float c[4], const uint32_t a[4],
                                        const uint32_t b[2]) {
    asm volatile(
        "mma.sync.aligned.m16n8k16.row.col.f32.f16.f16.f32 "
        "{%0,%1,%2,%3}, {%4,%5,%6,%7}, {%8,%9}, {%0,%1,%2,%3};"
        : "+f"(c[0]), "+f"(c[1]), "+f"(c[2]), "+f"(c[3])
        : "r"(a[0]), "r"(a[1]), "r"(a[2]), "r"(a[3]), "r"(b[0]), "r"(b[1]));
}

__device__ __forceinline__ void ldsm_x4(uint32_t r[4], uint32_t addr) {
    asm volatile("ldmatrix.sync.aligned.m8n8.x4.shared.b16 {%0,%1,%2,%3}, [%4];"
                 : "=r"(r[0]), "=r"(r[1]), "=r"(r[2]), "=r"(r[3]) : "r"(addr));
}
__device__ __forceinline__ void ldsm_x4_t(uint32_t r[4], uint32_t addr) {
    asm volatile("ldmatrix.sync.aligned.m8n8.x4.trans.shared.b16 {%0,%1,%2,%3}, [%4];"
                 : "=r"(r[0]), "=r"(r[1]), "=r"(r[2]), "=r"(r[3]) : "r"(addr));
}

#define CP_A16(dst, src) \
    asm volatile("cp.async.cg.shared.global [%0], [%1], 16;" \
                 :: "r"(dst), "l"(src) : "memory")
#define CP_COMMIT() asm volatile("cp.async.commit_group;" ::: "memory")
#define CP_WAIT0()  asm volatile("cp.async.wait_group 0;" ::: "memory")

__device__ __forceinline__ uint32_t packh2(float x, float y) {
    __half2 h = __float22half2_rn(make_float2(x, y));
    return *(uint32_t*)&h;
}

// MUFU exp2: 1 instruction/value. ex2(-huge) -> 0 exactly.
__device__ __forceinline__ float ex2(float y) {
    float r;
    asm("ex2.approx.ftz.f32 %0, %1;" : "=f"(r) : "f"(y));
    return r;
}

// Swizzle for 128-col 16-bit tiles (256B rows), 16B chunks (attention)
__device__ __forceinline__ uint32_t sw256(int row, int col) {
    int chunk = col >> 3;
    return (uint32_t)(row * 256 + (((chunk ^ (row & 7)) << 4) | ((col & 7) << 1)));
}
// Swizzle for 64-col fp16 tiles (128B rows), 8 chunks of 16B (GEMM)
__device__ __forceinline__ uint32_t sw128h(int row, int chunk) {
    return (uint32_t)(row * 128 + ((chunk ^ (row & 7)) << 4));
}

// ---------------------------------------------------------------------------
// Weight concat + fp16 convert + trig table (one launch)
// ---------------------------------------------------------------------------
__global__ void prep_kernel(const float* __restrict__ Wq,
                            const float* __restrict__ Wk,
                            const float* __restrict__ Wv,
                            const float* __restrict__ Wo)
{
    int i = blockIdx.x * blockDim.x + threadIdx.x;
    const int WCAT4 = 512 * DIM / 4;
    const int WO4   = DIM * 256 / 4;
    const int TRIG  = T_SEQ * 64;
    if (i < WCAT4) {
        int row = i >> 8;
        float4 v;
        if (row < 256)       v = ((const float4*)Wq)[i];
        else if (row < 384)  v = ((const float4*)Wk)[i - 256 * 256];
        else                 v = ((const float4*)Wv)[i - 384 * 256];
        uint2 w;
        w.x = packh2(v.x, v.y);
        w.y = packh2(v.z, v.w);
        *(uint2*)(g_w16 + i * 4) = w;
    } else if (i < WCAT4 + WO4) {
        int j = i - WCAT4;
        float4 v = ((const float4*)Wo)[j];
        uint2 w;
        w.x = packh2(v.x, v.y);
        w.y = packh2(v.z, v.w);
        *(uint2*)(g_wo16 + j * 4) = w;
    } else if (i < WCAT4 + WO4 + TRIG) {
        int j = i - WCAT4 - WO4;
        int t = j >> 6, k = j & 63;
        float theta = exp2f(-(float)k * (13.287712379549449f / 32.0f));
        float s, c;
        sincosf((float)t * theta, &s, &c);
        g_trig[j] = make_float2(c, s);
    }
}

// ---------------------------------------------------------------------------
// rope epilogue store (GEMM1)
// ---------------------------------------------------------------------------
__device__ __forceinline__ void rope_epi_store(int r, int c, float x0, float x1)
{
    const float qscale = 0.08838834764831845f * 1.4426950408889634f;
    int t = r & (T_SEQ - 1);
    if (c < 384) {
        int i = (c & 127) >> 1;
        float2 cs = g_trig[t * 64 + i];
        float y0 = x0 * cs.x - x1 * cs.y;
        float y1 = x1 * cs.x + x0 * cs.y;
        if (c < 256) {
            y0 *= qscale; y1 *= qscale;
            *(uint32_t*)(g_q16 + (size_t)r * 256 + c) = packh2(y0, y1);
        } else {
            *(uint32_t*)(g_k16 + (size_t)r * 128 + (c - 256)) = packh2(y0, y1);
        }
    } else {
        *(uint32_t*)(g_v16 + (size_t)r * 128 + (c - 384)) = packh2(x0, x1);
    }
}

// ---------------------------------------------------------------------------
// GEMM1 (frozen R16 WIN): qkv = x (fp32 -> single fp16 inline) * Wcat16^T.
// ---------------------------------------------------------------------------
#define GEMM_SMEM 65536

__global__ __launch_bounds__(256, 2)
void gemm_x_kernel(const float* __restrict__ X,
                   const __half* __restrict__ B16,
                   int M, int N, int K)
{
    extern __shared__ __align__(16) char smp[];
    const uint32_t sb = smem_u32(smp);

    const int tid = threadIdx.x;
    const int wid = tid >> 5;
    const int lane = tid & 31;
    const int m0 = blockIdx.x * 128;
    const int n0 = blockIdx.y * 128;
    const int wm = wid & 3;
    const int wn = wid >> 2;

    float acc[2][8][4];
#pragma unroll
    for (int mf = 0; mf < 2; mf++)
#pragma unroll
        for (int nf = 0; nf < 8; nf++)
#pragma unroll
            for (int q = 0; q < 4; q++) acc[mf][nf][q] = 0.f;

    const int KT = K >> 6;    // 16

    auto fillB = [&](int buf, int kt) {
        const uint32_t bbase = sb + buf * 32768 + 16384;
#pragma unroll
        for (int i = 0; i < 4; i++) {
            int u = tid + i * 256;
            int row = u >> 3, ch = u & 7;
            CP_A16(bbase + sw128h(row, ch),
                   B16 + (size_t)(n0 + row) * K + kt * 64 + ch * 8);
        }
        CP_COMMIT();
    };

    auto ldgA = [&](int kt, int bsel, float4 vr[4]) {
#pragma unroll
        for (int i = 0; i < 4; i++) {
            int u = tid + (bsel * 4 + i) * 256;
            int row = u >> 4, q4 = u & 15;
            vr[i] = *(const float4*)(X + (size_t)(m0 + row) * K + kt * 64 + q4 * 4);
        }
    };
    auto stsA = [&](int buf, int bsel, const float4 vr[4]) {
#pragma unroll
        for (int i = 0; i < 4; i++) {
            int u = tid + (bsel * 4 + i) * 256;
            int row = u >> 4, q4 = u & 15;
            uint32_t off = sw128h(row, q4 >> 1) + (q4 & 1) * 8;
            *(uint2*)(smp + (off + buf * 32768)) =
                make_uint2(packh2(vr[i].x, vr[i].y), packh2(vr[i].z, vr[i].w));
        }
    };

    {
        float4 v0[4], v1[4];
        ldgA(0, 0, v0);
        ldgA(0, 1, v1);
        fillB(0, 0);
        stsA(0, 0, v0);
        stsA(0, 1, v1);
        CP_WAIT0();
        __syncthreads();
    }

    for (int kt = 0; kt < KT; kt++) {
        const int buf = kt & 1;
        const bool pre = (kt + 1 < KT);

        float4 vr[4];
        if (pre) {
            fillB(buf ^ 1, kt + 1);
            ldgA(kt + 1, 0, vr);
        }

        const uint32_t ab = sb + buf * 32768;
        const uint32_t bb = ab + 16384;

#pragma unroll
        for (int ks = 0; ks < 2; ks++) {
            uint32_t ah[2][4];
#pragma unroll
            for (int mf = 0; mf < 2; mf++) {
                int row = wm * 32 + mf * 16 + (lane & 15);
                int chunk = ks * 2 + (lane >> 4);
                ldsm_x4(ah[mf], ab + sw128h(row, chunk));
            }
            uint32_t bh[8][2];
#pragma unroll
            for (int np = 0; np < 4; np++) {
                int row = wn * 64 + np * 16 + ((lane >> 4) << 3) + (lane & 7);
                int chunk = ks * 2 + ((lane >> 3) & 1);
                uint32_t t[4];
                ldsm_x4(t, bb + sw128h(row, chunk));
                bh[np * 2][0] = t[0]; bh[np * 2][1] = t[1];
                bh[np * 2 + 1][0] = t[2]; bh[np * 2 + 1][1] = t[3];
            }
#pragma unroll
            for (int mf = 0; mf < 2; mf++)
#pragma unroll
                for (int nf = 0; nf < 8; nf++)
                    mma_f16(acc[mf][nf], ah[mf], bh[nf]);
        }

        if (pre) {
            stsA(buf ^ 1, 0, vr);
            ldgA(kt + 1, 1, vr);
        }

#pragma unroll
        for (int ks = 2; ks < 4; ks++) {
            uint32_t ah[2][4];
#pragma unroll
            for (int mf = 0; mf < 2; mf++) {
                int row = wm * 32 + mf * 16 + (lane & 15);
                int chunk = ks * 2 + (lane >> 4);
                ldsm_x4(ah[mf], ab + sw128h(row, chunk));
            }
            uint32_t bh[8][2];
#pragma unroll
            for (int np = 0; np < 4; np++) {
                int row = wn * 64 + np * 16 + ((lane >> 4) << 3) + (lane & 7);
                int chunk = ks * 2 + ((lane >> 3) & 1);
                uint32_t t[4];
                ldsm_x4(t, bb + sw128h(row, chunk));
                bh[np * 2][0] = t[0]; bh[np * 2][1] = t[1];
                bh[np * 2 + 1][0] = t[2]; bh[np * 2 + 1][1] = t[3];
            }
#pragma unroll
            for (int mf = 0; mf < 2; mf++)
#pragma unroll
                for (int nf = 0; nf < 8; nf++)
                    mma_f16(acc[mf][nf], ah[mf], bh[nf]);
        }

        if (pre) stsA(buf ^ 1, 1, vr);

        if (pre) {
            CP_WAIT0();
        }
        __syncthreads();
    }

#pragma unroll
    for (int mf = 0; mf < 2; mf++)
#pragma unroll
        for (int nf = 0; nf < 8; nf++) {
            int row = m0 + wm * 32 + mf * 16 + (lane >> 2);
            int col = n0 + wn * 64 + nf * 8 + (lane & 3) * 2;
            rope_epi_store(row,     col, acc[mf][nf][0], acc[mf][nf][1]);
            rope_epi_store(row + 8, col, acc[mf][nf][2], acc[mf][nf][3]);
        }
}

// ---------------------------------------------------------------------------
// GEMM2 (frozen R15 WIN): out = A16 * Wo16^T, fp32 C. Single fp16 A.
// ---------------------------------------------------------------------------
#define GEMM2_SMEM 65536

__global__ __launch_bounds__(256, 2)
void gemm_f16s_kernel(const __half* __restrict__ A16,
                      const __half* __restrict__ B16,
                      float* __restrict__ C, int M, int N, int K, int ldc)
{
    extern __shared__ __align__(16) char smp[];
    const uint32_t sb = smem_u32(smp);

    const int tid = threadIdx.x;
    const int wid = tid >> 5;
    const int lane = tid & 31;
    const int m0 = blockIdx.x * 128;
    const int n0 = blockIdx.y * 128;
    const int wm = wid & 3;
    const int wn = wid >> 2;

    float acc[2][8][4];
#pragma unroll
    for (int mf = 0; mf < 2; mf++)
#pragma unroll
        for (int nf = 0; nf < 8; nf++)
#pragma unroll
            for (int q = 0; q < 4; q++) acc[mf][nf][q] = 0.f;

    const int KT = K >> 6;

    auto fill = [&](int buf, int kt) {
        const uint32_t base = sb + buf * 32768;
#pragma unroll
        for (int i = 0; i < 4; i++) {
            int u = tid + i * 256;
            int row = u >> 3, ch = u & 7;
            uint32_t off = sw128h(row, ch);
            size_t sA = (size_t)(m0 + row) * K + kt * 64 + ch * 8;
            size_t sB = (size_t)(n0 + row) * K + kt * 64 + ch * 8;
            CP_A16(base + off,         A16 + sA);
            CP_A16(base + 16384 + off, B16 + sB);
        }
        CP_COMMIT();
    };

    fill(0, 0);

    for (int kt = 0; kt < KT; kt++) {
        const int buf = kt & 1;
        CP_WAIT0();
        __syncthreads();
        if (kt + 1 < KT) fill(buf ^ 1, kt + 1);

        const uint32_t ab = sb + buf * 32768;
        const uint32_t bb = ab + 16384;
#pragma unroll
        for (int ks = 0; ks < 4; ks++) {
            uint32_t ah[2][4];
#pragma unroll
            for (int mf = 0; mf < 2; mf++) {
                int row = wm * 32 + mf * 16 + (lane & 15);
                int chunk = ks * 2 + (lane >> 4);
                ldsm_x4(ah[mf], ab + sw128h(row, chunk));
            }
            uint32_t bh[8][2];
#pragma unroll
            for (int np = 0; np < 4; np++) {
                int row = wn * 64 + np * 16 + ((lane >> 4) << 3) + (lane & 7);
                int chunk = ks * 2 + ((lane >> 3) & 1);
                uint32_t t[4];
                ldsm_x4(t, bb + sw128h(row, chunk));
                bh[np * 2][0] = t[0]; bh[np * 2][1] = t[1];
                bh[np * 2 + 1][0] = t[2]; bh[np * 2 + 1][1] = t[3];
            }
#pragma unroll
            for (int mf = 0; mf < 2; mf++)
#pragma unroll
                for (int nf = 0; nf < 8; nf++)
                    mma_f16(acc[mf][nf], ah[mf], bh[nf]);
        }
    }

#pragma unroll
    for (int mf = 0; mf < 2; mf++)
#pragma unroll
        for (int nf = 0; nf < 8; nf++) {
            int row = m0 + wm * 32 + mf * 16 + (lane >> 2);
            int col = n0 + wn * 64 + nf * 8 + (lane & 3) * 2;
            *(float2*)(C + (size_t)row * ldc + col) =
                make_float2(acc[mf][nf][0], acc[mf][nf][1]);
            *(float2*)(C + (size_t)(row + 8) * ldc + col) =
                make_float2(acc[mf][nf][2], acc[mf][nf][3]);
        }
}

// ---------------------------------------------------------------------------
// Flash attention, SPLIT-KV (2 splits). Each CTA covers half the causal KV
// range of one (head, m-tile); partials (O fp32, m, l) to scratch.
// Core pipeline identical to R12/R16 WIN: triple-buffered K/V, MUFU ex2.
// grid.x = 64: split = bx&1, tile index = bx>>1 (orbit-balanced).
// ---------------------------------------------------------------------------
#define ATT2_SMEM 98304

__global__ __launch_bounds__(128, 2)
void attn_split_kernel(const __half* __restrict__ q_g,
                       const __half* __restrict__ k_g,
                       const __half* __restrict__ v_g, int T)
{
    extern __shared__ __align__(16) char smp[];
    const uint32_t sb = smem_u32(smp);

    const int tid = threadIdx.x;
    const int wid = tid >> 5;
    const int lane = tid & 31;
    const int bh = blockIdx.y;
    const int b  = bh >> 1;
    const int h  = bh & 1;

    const int split = blockIdx.x & 1;
    const int txi = blockIdx.x >> 1;
    const int oo = txi & 3;
    const int qq = txi >> 2;
    const int pp_ = (qq & 1) ? (qq ^ 4) : qq;
    const int mt = (pp_ & 1) ? (4 * oo + (pp_ >> 1)) : (31 - 4 * oo - (pp_ >> 1));
    const int m0 = mt * 64;

    const int n_tot = mt + 1;
    const int nh = (n_tot + 1) >> 1;
    const int j0 = split ? nh : 0;
    const int j1 = split ? n_tot : nh;

    const size_t rb = (size_t)b * T;
    float* po = g_po + (size_t)split * (BT_MAX * 256);
    float* pm = g_pm + (size_t)split * (BT_MAX * 2);
    float* pl = g_pl + (size_t)split * (BT_MAX * 2);

    if (j0 >= j1) {
        // empty split: l=0, m=-huge; O ignored (weight 0 in combine)
        if (tid < 64) {
            size_t prow = rb + m0 + tid;
            pm[prow * 2 + h] = -1e30f;
            pl[prow * 2 + h] = 0.f;
        }
        return;
    }

    auto KB = [&](int bf) { return sb + bf * 16384; };
    auto VB = [&](int bf) { return sb + 49152 + bf * 16384; };

    auto fillKV = [&](int bf, int j) {
        const uint32_t kb = KB(bf);
        const uint32_t vb = VB(bf);
        const int n0v = j * 64;
#pragma unroll
        for (int i = 0; i < 8; i++) {
            int u = tid + i * 128;
            int row = u >> 4, ch = u & 15;
            uint32_t off = sw256(row, ch * 8);
            size_t src = (size_t)(rb + n0v + row) * 128 + ch * 8;
            CP_A16(kb + off, k_g + src);
            CP_A16(vb + off, v_g + src);
        }
        CP_COMMIT();
    };

    // ---- prologue: stage Q (into V_2 slot) + fill KV tile j0 ----
    {
        const uint32_t qstage = VB(2);
#pragma unroll
        for (int i = 0; i < 8; i++) {
            int u = tid + i * 128;
            int row = u >> 4, ch = u & 15;
            uint32_t off = sw256(row, ch * 8);
            size_t src = (rb + m0 + row) * 256 + h * 128 + ch * 8;
            CP_A16(qstage + off, q_g + src);
        }
        const int n0v = j0 * 64;
#pragma unroll
        for (int i = 0; i < 8; i++) {
            int u = tid + i * 128;
            int row = u >> 4, ch = u & 15;
            uint32_t off = sw256(row, ch * 8);
            size_t src = (size_t)(rb + n0v + row) * 128 + ch * 8;
            CP_A16(KB(0) + off, k_g + src);
            CP_A16(VB(0) + off, v_g + src);
        }
        CP_COMMIT();
        CP_WAIT0();
        __syncthreads();
    }

    uint32_t qf[8][4];
#pragma unroll
    for (int ks = 0; ks < 8; ks++) {
        int row = wid * 16 + (lane & 15);
        int chunk = ks * 2 + (lane >> 4);
        ldsm_x4(qf[ks], VB(2) + sw256(row, chunk * 8));
    }
    // buf 2 is first refilled inside the loop, after a barrier — safe.

    if (j0 + 1 < j1) fillKV(1, j0 + 1);

    float mr0 = -1e30f, mr1 = -1e30f, lr0 = 0.f, lr1 = 0.f;
    float oacc[16][4];
#pragma unroll
    for (int nf = 0; nf < 16; nf++)
#pragma unroll
        for (int q = 0; q < 4; q++) oacc[nf][q] = 0.f;

    uint32_t pp[4][4];

    auto computeS = [&](uint32_t kb, float sacc[8][4]) {
#pragma unroll
        for (int nf = 0; nf < 8; nf++)
#pragma unroll
            for (int q = 0; q < 4; q++) sacc[nf][q] = 0.f;
#pragma unroll
        for (int ks = 0; ks < 8; ks++) {
#pragma unroll
            for (int ng = 0; ng < 4; ng++) {
                int row = ng * 16 + ((lane >> 4) << 3) + (lane & 7);
                int chunk = ks * 2 + ((lane >> 3) & 1);
                uint32_t t[4];
                ldsm_x4(t, kb + sw256(row, chunk * 8));
                uint32_t b0[2] = {t[0], t[1]}, b1[2] = {t[2], t[3]};
                mma_f16(sacc[ng * 2],     qf[ks], b0);
                mma_f16(sacc[ng * 2 + 1], qf[ks], b1);
            }
        }
    };

    auto softmax_pack = [&](float sacc[8][4], int jj) {
        if (jj == mt) {
            int grow0 = m0 + wid * 16 + (lane >> 2);
            int grow1 = grow0 + 8;
            int cbase = jj * 64 + (lane & 3) * 2;
#pragma unroll
            for (int nf = 0; nf < 8; nf++) {
                int c = cbase + nf * 8;
                if (c     > grow0) sacc[nf][0] = -1e30f;
                if (c + 1 > grow0) sacc[nf][1] = -1e30f;
                if (c     > grow1) sacc[nf][2] = -1e30f;
                if (c + 1 > grow1) sacc[nf][3] = -1e30f;
            }
        }
        float mx0 = -1e30f, mx1 = -1e30f;
#pragma unroll
        for (int nf = 0; nf < 8; nf++) {
            mx0 = fmaxf(mx0, fmaxf(sacc[nf][0], sacc[nf][1]));
            mx1 = fmaxf(mx1, fmaxf(sacc[nf][2], sacc[nf][3]));
        }
        mx0 = fmaxf(mx0, __shfl_xor_sync(0xffffffffu, mx0, 1));
        mx0 = fmaxf(mx0, __shfl_xor_sync(0xffffffffu, mx0, 2));
        mx1 = fmaxf(mx1, __shfl_xor_sync(0xffffffffu, mx1, 1));
        mx1 = fmaxf(mx1, __shfl_xor_sync(0xffffffffu, mx1, 2));

        float mn0 = fmaxf(mr0, mx0), mn1 = fmaxf(mr1, mx1);
        float corr0 = ex2(mr0 - mn0), corr1 = ex2(mr1 - mn1);
        mr0 = mn0; mr1 = mn1;

        float sum0 = 0.f, sum1 = 0.f;
#pragma unroll
        for (int nf = 0; nf < 8; nf++) {
            sacc[nf][0] = ex2(sacc[nf][0] - mn0);
            sacc[nf][1] = ex2(sacc[nf][1] - mn0);
            sacc[nf][2] = ex2(sacc[nf][2] - mn1);
            sacc[nf][3] = ex2(sacc[nf][3] - mn1);
            sum0 += sacc[nf][0] + sacc[nf][1];
            sum1 += sacc[nf][2] + sacc[nf][3];
        }
        sum0 += __shfl_xor_sync(0xffffffffu, sum0, 1);
        sum0 += __shfl_xor_sync(0xffffffffu, sum0, 2);
        sum1 += __shfl_xor_sync(0xffffffffu, sum1, 1);
        sum1 += __shfl_xor_sync(0xffffffffu, sum1, 2);
        lr0 = lr0 * corr0 + sum0;
        lr1 = lr1 * corr1 + sum1;

        if (__any_sync(0xffffffffu, (corr0 < 1.0f) | (corr1 < 1.0f))) {
#pragma unroll
            for (int nf = 0; nf < 16; nf++) {
                oacc[nf][0] *= corr0; oacc[nf][1] *= corr0;
                oacc[nf][2] *= corr1; oacc[nf][3] *= corr1;
            }
        }
#pragma unroll
        for (int kc = 0; kc < 4; kc++) {
            pp[kc][0] = packh2(sacc[2 * kc][0],     sacc[2 * kc][1]);
            pp[kc][1] = packh2(sacc[2 * kc][2],     sacc[2 * kc][3]);
            pp[kc][2] = packh2(sacc[2 * kc + 1][0], sacc[2 * kc + 1][1]);
            pp[kc][3] = packh2(sacc[2 * kc + 1][2], sacc[2 * kc + 1][3]);
        }
    };

    auto computePV = [&](uint32_t vb) {
#pragma unroll
        for (int ks2 = 0; ks2 < 4; ks2++) {
            int vrow = ks2 * 16 + (lane & 15);
#pragma unroll
            for (int g = 0; g < 8; g++) {
                int chunk = g * 2 + (lane >> 4);
                uint32_t vh[4];
                ldsm_x4_t(vh, vb + sw256(vrow, chunk * 8));
                uint32_t vh0[2] = {vh[0], vh[1]}, vh1[2] = {vh[2], vh[3]};
                mma_f16(oacc[g * 2],     pp[ks2], vh0);
                mma_f16(oacc[g * 2 + 1], pp[ks2], vh1);
            }
        }
    };

    // ---- prologue compute: S(j0) -> P(j0) ----
    {
        float sacc[8][4];
        computeS(KB(0), sacc);
        softmax_pack(sacc, j0);
    }

    // ---- pipelined main loop: PV(j) + S(j+1), local buffer idx (j-j0)%3 ----
    for (int jj = j0; jj < j1 - 1; jj++) {
        const int i = jj - j0;
        CP_WAIT0();
        __syncthreads();
        if (jj + 2 < j1) fillKV((i + 2) % 3, jj + 2);

        float sacc[8][4];
        computeS(KB((i + 1) % 3), sacc);
        computePV(VB(i % 3));

        softmax_pack(sacc, jj + 1);
    }

    // ---- final PV ----
    computePV(VB((j1 - 1 - j0) % 3));

    // ---- epilogue: store fp32 partials (un-normalized O, m, l) ----
    size_t prow = rb + m0 + wid * 16 + (lane >> 2);
#pragma unroll
    for (int nf = 0; nf < 16; nf++) {
        int col = h * 128 + nf * 8 + (lane & 3) * 2;
        *(float2*)(po + prow * 256 + col) =
            make_float2(oacc[nf][0], oacc[nf][1]);
        *(float2*)(po + (prow + 8) * 256 + col) =
            make_float2(oacc[nf][2], oacc[nf][3]);
    }
    if ((lane & 3) == 0) {
        pm[prow * 2 + h] = mr0;
        pl[prow * 2 + h] = lr0;
        pm[(prow + 8) * 2 + h] = mr1;
        pl[(prow + 8) * 2 + h] = lr1;
    }
}

// ---------------------------------------------------------------------------
// Split-KV combine: O = (O1*e^{m1-m} + O2*e^{m2-m}) / l  -> fp16 g_ath
// ---------------------------------------------------------------------------
__global__ void combine_kernel()
{
    int idx = blockIdx.x * blockDim.x + threadIdx.x;   // BT*64 float4 groups
    if (idx >= BT_MAX * 64) return;
    int row = idx >> 6;
    int g   = idx & 63;
    int h   = g >> 5;

    float m1 = g_pm[row * 2 + h];
    float m2 = g_pm[BT_MAX * 2 + row * 2 + h];
    float l1 = g_pl[row * 2 + h];
    float l2 = g_pl[BT_MAX * 2 + row * 2 + h];
    float m  = fmaxf(m1, m2);
    float e1 = ex2(m1 - m), e2 = ex2(m2 - m);
    float inv = 1.0f / fmaf(l1, e1, l2 * e2);
    float s1 = e1 * inv, s2 = e2 * inv;

    size_t off = (size_t)row * 256 + g * 4;
    float4 o1 = *(const float4*)(g_po + off);
    float4 o2 = *(const float4*)(g_po + BT_MAX * 256 + off);
    float r0 = fmaf(o1.x, s1, o2.x * s2);
    float r1 = fmaf(o1.y, s1, o2.y * s2);
    float r2 = fmaf(o1.z, s1, o2.z * s2);
    float r3 = fmaf(o1.w, s1, o2.w * s2);
    *(uint2*)(g_ath + off) = make_uint2(packh2(r0, r1), packh2(r2, r3));
}

// ---------------------------------------------------------------------------
extern "C" void kernel_launch(void* const* d_in, const int* in_sizes, int n_in,
                              void* d_out, int out_size)
{
    const float* x  = (const float*)d_in[0];
    const float* Wq = (const float*)d_in[1];
    const float* Wk = (const float*)d_in[2];
    const float* Wv = (const float*)d_in[3];
    const float* Wo = (const float*)d_in[4];

    const int BT = in_sizes[0] / DIM;  // 8192
    const int T  = T_SEQ;
    const int B  = BT / T;

    __half *q16, *k16, *v16, *ath, *w16, *wo16;
    cudaGetSymbolAddress((void**)&q16,  g_q16);
    cudaGetSymbolAddress((void**)&k16,  g_k16);
    cudaGetSymbolAddress((void**)&v16,  g_v16);
    cudaGetSymbolAddress((void**)&ath,  g_ath);
    cudaGetSymbolAddress((void**)&w16,  g_w16);
    cudaGetSymbolAddress((void**)&wo16, g_wo16);

    cudaFuncSetAttribute(gemm_x_kernel,
                         cudaFuncAttributeMaxDynamicSharedMemorySize, GEMM_SMEM);
    cudaFuncSetAttribute(gemm_f16s_kernel,
                         cudaFuncAttributeMaxDynamicSharedMemorySize, GEMM2_SMEM);
    cudaFuncSetAttribute(attn_split_kernel,
                         cudaFuncAttributeMaxDynamicSharedMemorySize, ATT2_SMEM);

    // 1) prep (weights + trig)
    {
        int wt = 512 * DIM / 4 + DIM * 256 / 4 + T_SEQ * 64;
        prep_kernel<<<(wt + 255) / 256, 256>>>(Wq, Wk, Wv, Wo);
    }

    // 2) fused QKV projection (x -> single fp16 inline) + rope epilogue
    {
        dim3 grid(BT / 128, 512 / 128);
        gemm_x_kernel<<<grid, 256, GEMM_SMEM>>>(x, w16, BT, 512, DIM);
    }

    // 3) flash attention, split-KV (2 splits)
    {
        dim3 grid(T / 64 * 2, B * NKV);
        attn_split_kernel<<<grid, 128, ATT2_SMEM>>>(q16, k16, v16, T);
    }

    // 3b) combine partials -> fp16
    {
        int tot = BT_MAX * 64;
        combine_kernel<<<(tot + 255) / 256, 256>>>();
    }

    // 4) output projection (single-fp16 A)
    {
        dim3 grid(BT / 128, DIM / 128);
        gemm_f16s_kernel<<<grid, 256, GEMM2_SMEM>>>(ath, wo16, (float*)d_out,
                                                    BT, DIM, 256, DIM);
    }
}